// round 4
// baseline (speedup 1.0000x reference)
#include <cuda_runtime.h>
#include <cstdint>

// ---------------- problem constants ----------------
constexpr int Nn   = 50000;          // nodes
constexpr int Ee   = 800000;         // edges (w/o self loops)
constexpr int ET   = Ee + Nn;        // edges incl. self loops
constexpr int IND  = 128;            // input dim
constexpr int C0   = 128;            // layer0 out channels (2 heads * 64)
constexpr int OUTD = 64;             // layer1 out channels (1 head)
constexpr float NEG_SLOPE = 0.2f;
constexpr float BN_EPS    = 1e-5f;

constexpr int SCAN_B = 1024;
constexpr int NB1    = (Nn + SCAN_B - 1) / SCAN_B;   // 49
constexpr int BN_BLOCKS = 512;

// ---------------- device scratch ----------------
__device__ float4 g_h0[Nn * C0 / 4];     // x@W0
__device__ float4 g_x1[Nn * C0 / 4];     // layer0 out -> BN/ELU
__device__ float4 g_h1[Nn * OUTD / 4];   // x1@W1
__device__ float  g_a0s[Nn * 2];
__device__ float  g_a0d[Nn * 2];
__device__ float  g_a1s[Nn];
__device__ float  g_a1d[Nn];
__device__ float  g_bps[BN_BLOCKS * C0]; // BN partial sums
__device__ float  g_bpq[BN_BLOCKS * C0]; // BN partial sum-of-squares
__device__ float  g_bnsum[C0];
__device__ float  g_bnsq [C0];
// CSR
__device__ int    g_deg   [Nn];
__device__ int    g_cnt   [Nn];
__device__ int    g_incl  [Nn];
__device__ int    g_rowptr[Nn + 1];
__device__ int    g_adj   [ET];
__device__ int    g_bsum  [NB1];
__device__ int    g_bsums [NB1];

__device__ __forceinline__ float lrelu(float e) {
    return e > 0.f ? e : NEG_SLOPE * e;
}

// ---------------- zero ----------------
__global__ void zero_int_kernel(int* p, int n) {
    int i = blockIdx.x * blockDim.x + threadIdx.x;
    for (; i < n; i += gridDim.x * blockDim.x) p[i] = 0;
}

// ---------------- CSR build ----------------
__global__ void deg_kernel(const int* __restrict__ ei, int* __restrict__ deg) {
    int i = blockIdx.x * blockDim.x + threadIdx.x;
    if (i >= ET) return;
    int dst = (i < Ee) ? ei[Ee + i] : (i - Ee);
    atomicAdd(&deg[dst], 1);
}

__global__ void scan1_kernel(const int* __restrict__ deg,
                             int* __restrict__ incl, int* __restrict__ bsum) {
    __shared__ int sh[SCAN_B];
    int tid = threadIdx.x;
    int i = blockIdx.x * SCAN_B + tid;
    sh[tid] = (i < Nn) ? deg[i] : 0;
    __syncthreads();
#pragma unroll
    for (int off = 1; off < SCAN_B; off <<= 1) {
        int t = (tid >= off) ? sh[tid - off] : 0;
        __syncthreads();
        sh[tid] += t;
        __syncthreads();
    }
    if (i < Nn) incl[i] = sh[tid];
    if (tid == SCAN_B - 1) bsum[blockIdx.x] = sh[tid];
}

__global__ void scan2_kernel(const int* __restrict__ bsum, int* __restrict__ bsums) {
    __shared__ int sh[64];
    int tid = threadIdx.x;                   // 64 threads, NB1 <= 64
    sh[tid] = (tid < NB1) ? bsum[tid] : 0;
    __syncthreads();
#pragma unroll
    for (int off = 1; off < 64; off <<= 1) {
        int t = (tid >= off) ? sh[tid - off] : 0;
        __syncthreads();
        sh[tid] += t;
        __syncthreads();
    }
    if (tid < NB1) bsums[tid] = sh[tid];
}

__global__ void scan3_kernel(const int* __restrict__ incl,
                             const int* __restrict__ bsums,
                             int* __restrict__ rowptr) {
    int i = blockIdx.x * blockDim.x + threadIdx.x;
    if (i == 0) rowptr[0] = 0;
    if (i >= Nn) return;
    int b = i / SCAN_B;
    int off = (b > 0) ? bsums[b - 1] : 0;
    rowptr[i + 1] = incl[i] + off;
}

__global__ void fill_kernel(const int* __restrict__ ei,
                            const int* __restrict__ rowptr,
                            int* __restrict__ cnt, int* __restrict__ adj) {
    int i = blockIdx.x * blockDim.x + threadIdx.x;
    if (i >= ET) return;
    int src, dst;
    if (i < Ee) { src = ei[i]; dst = ei[Ee + i]; }
    else        { src = dst = i - Ee; }
    int pos = rowptr[dst] + atomicAdd(&cnt[dst], 1);
    adj[pos] = src;
}

// ---------------- GEMM: Y[n, OUTC] = X[n, KD] @ W[KD, OUTC] ----------------
template<int KD, int OUTC, int R>
__global__ void gemm_kernel(const float* __restrict__ X,
                            const float* __restrict__ W,
                            float* __restrict__ Y, int nrows) {
    __shared__ float4 xs4[R * KD / 4];
    float* xs = reinterpret_cast<float*>(xs4);
    const int row0 = blockIdx.x * R;
    const int col  = threadIdx.x;                    // blockDim.x == OUTC

    for (int i = threadIdx.x; i < R * KD; i += OUTC) {
        int r = i / KD, k = i - r * KD;
        int row = row0 + r;
        xs[i] = (row < nrows) ? X[row * KD + k] : 0.f;
    }
    __syncthreads();

    float acc[R];
#pragma unroll
    for (int r = 0; r < R; r++) acc[r] = 0.f;

#pragma unroll 4
    for (int k = 0; k < KD; k += 4) {
        float w0 = W[(k + 0) * OUTC + col];
        float w1 = W[(k + 1) * OUTC + col];
        float w2 = W[(k + 2) * OUTC + col];
        float w3 = W[(k + 3) * OUTC + col];
#pragma unroll
        for (int r = 0; r < R; r++) {
            float4 x4 = xs4[(r * KD + k) >> 2];
            acc[r] += x4.x * w0 + x4.y * w1 + x4.z * w2 + x4.w * w3;
        }
    }
#pragma unroll
    for (int r = 0; r < R; r++) {
        int row = row0 + r;
        if (row < nrows) Y[row * OUTC + col] = acc[r];
    }
}

// ---------------- attention dot products (warp per node) ----------------
template<int CH, int H>
__global__ void attdot_kernel(const float* __restrict__ hfeat,
                              const float* __restrict__ att_src,
                              const float* __restrict__ att_dst,
                              float* __restrict__ a_s,
                              float* __restrict__ a_d) {
    int warp = (blockIdx.x * blockDim.x + threadIdx.x) >> 5;
    int lane = threadIdx.x & 31;
    if (warp >= Nn) return;

    float sh[H], dh[H];
#pragma unroll
    for (int h = 0; h < H; h++) { sh[h] = 0.f; dh[h] = 0.f; }

#pragma unroll
    for (int j = 0; j < CH / 32; j++) {
        int c = lane + 32 * j;
        constexpr int CPH = CH / H;
        int h = (32 * j) / CPH;                  // compile-time per j
        float v = hfeat[warp * CH + c];
        sh[h] += v * att_src[c];
        dh[h] += v * att_dst[c];
    }
#pragma unroll
    for (int h = 0; h < H; h++) {
#pragma unroll
        for (int off = 16; off > 0; off >>= 1) {
            sh[h] += __shfl_xor_sync(0xffffffffu, sh[h], off);
            dh[h] += __shfl_xor_sync(0xffffffffu, dh[h], off);
        }
    }
    if (lane == 0) {
#pragma unroll
        for (int h = 0; h < H; h++) {
            a_s[warp * H + h] = sh[h];
            a_d[warp * H + h] = dh[h];
        }
    }
}

// ------- layer0: fused segment softmax + gather-aggregate + bias (warp/node) -
__global__ void agg0_kernel(const int* __restrict__ rowptr,
                            const int* __restrict__ adj,
                            const float* __restrict__ a_s,
                            const float* __restrict__ a_d,
                            const float4* __restrict__ h,
                            float4* __restrict__ out,
                            const float* __restrict__ bias) {
    int node = (blockIdx.x * blockDim.x + threadIdx.x) >> 5;
    int lane = threadIdx.x & 31;
    if (node >= Nn) return;
    const int beg = rowptr[node], end = rowptr[node + 1];
    const float ad0 = a_d[node * 2 + 0];
    const float ad1 = a_d[node * 2 + 1];

    // pass 1: segment max (lane-strided + butterfly reduce)
    float m0 = -1e30f, m1 = -1e30f;
    for (int j = beg + lane; j < end; j += 32) {
        int s = adj[j];
        m0 = fmaxf(m0, lrelu(a_s[s * 2 + 0] + ad0));
        m1 = fmaxf(m1, lrelu(a_s[s * 2 + 1] + ad1));
    }
#pragma unroll
    for (int off = 16; off > 0; off >>= 1) {
        m0 = fmaxf(m0, __shfl_xor_sync(0xffffffffu, m0, off));
        m1 = fmaxf(m1, __shfl_xor_sync(0xffffffffu, m1, off));
    }

    // pass 2: serial edge loop, 32 lanes cover the 128 channels (4 each)
    const bool hi = (lane >= 16);        // lanes 16..31 -> head 1 channels
    float den0 = 0.f, den1 = 0.f;
    float4 acc = make_float4(0.f, 0.f, 0.f, 0.f);
    for (int j = beg; j < end; j++) {
        int s = adj[j];
        float ex0 = __expf(lrelu(a_s[s * 2 + 0] + ad0) - m0);
        float ex1 = __expf(lrelu(a_s[s * 2 + 1] + ad1) - m1);
        den0 += ex0; den1 += ex1;
        float sc = hi ? ex1 : ex0;
        float4 v = h[(size_t)s * (C0 / 4) + lane];
        acc.x += v.x * sc; acc.y += v.y * sc;
        acc.z += v.z * sc; acc.w += v.w * sc;
    }
    float inv = 1.f / ((hi ? den1 : den0) + 1e-16f);
    int c = lane * 4;
    float4 b4 = *reinterpret_cast<const float4*>(bias + c);
    float4 o;
    o.x = acc.x * inv + b4.x;
    o.y = acc.y * inv + b4.y;
    o.z = acc.z * inv + b4.z;
    o.w = acc.w * inv + b4.w;
    out[(size_t)node * (C0 / 4) + lane] = o;
}

// ------- layer1: fused segment softmax + gather-aggregate + bias -------------
__global__ void agg1_kernel(const int* __restrict__ rowptr,
                            const int* __restrict__ adj,
                            const float* __restrict__ a_s,
                            const float* __restrict__ a_d,
                            const float2* __restrict__ h,
                            float2* __restrict__ out,
                            const float* __restrict__ bias) {
    int node = (blockIdx.x * blockDim.x + threadIdx.x) >> 5;
    int lane = threadIdx.x & 31;
    if (node >= Nn) return;
    const int beg = rowptr[node], end = rowptr[node + 1];
    const float ad = a_d[node];

    float m = -1e30f;
    for (int j = beg + lane; j < end; j += 32) {
        int s = adj[j];
        m = fmaxf(m, lrelu(a_s[s] + ad));
    }
#pragma unroll
    for (int off = 16; off > 0; off >>= 1)
        m = fmaxf(m, __shfl_xor_sync(0xffffffffu, m, off));

    float den = 0.f;
    float2 acc = make_float2(0.f, 0.f);
    for (int j = beg; j < end; j++) {
        int s = adj[j];
        float ex = __expf(lrelu(a_s[s] + ad) - m);
        den += ex;
        float2 v = h[(size_t)s * (OUTD / 2) + lane];
        acc.x += v.x * ex; acc.y += v.y * ex;
    }
    float inv = 1.f / (den + 1e-16f);
    int c = lane * 2;
    float2 o;
    o.x = acc.x * inv + bias[c + 0];
    o.y = acc.y * inv + bias[c + 1];
    out[(size_t)node * (OUTD / 2) + lane] = o;
}

// ---------------- BN partial statistics (deterministic) ----------------
__global__ void bnsum_kernel(const float* __restrict__ x,
                             float* __restrict__ bps, float* __restrict__ bpq) {
    int c = threadIdx.x;                         // blockDim.x == 128
    float lsum = 0.f, lsq = 0.f;
    for (int row = blockIdx.x; row < Nn; row += gridDim.x) {
        float v = x[(size_t)row * C0 + c];
        lsum += v;
        lsq  += v * v;
    }
    bps[blockIdx.x * C0 + c] = lsum;
    bpq[blockIdx.x * C0 + c] = lsq;
}

__global__ void bnred_kernel(const float* __restrict__ bps,
                             const float* __restrict__ bpq,
                             float* __restrict__ bnsum, float* __restrict__ bnsq) {
    int c = threadIdx.x;                         // one block of 128 threads
    float s = 0.f, q = 0.f;
    for (int b = 0; b < BN_BLOCKS; b++) {
        s += bps[b * C0 + c];
        q += bpq[b * C0 + c];
    }
    bnsum[c] = s;
    bnsq[c]  = q;
}

// ---------------- BN apply + ELU ----------------
__global__ void bn_elu_kernel(float* __restrict__ x,
                              const float* __restrict__ bnsum,
                              const float* __restrict__ bnsq,
                              const float* __restrict__ gamma,
                              const float* __restrict__ beta) {
    int i = blockIdx.x * blockDim.x + threadIdx.x;
    int stride = gridDim.x * blockDim.x;
    const float invN = 1.0f / (float)Nn;
    for (; i < Nn * C0; i += stride) {
        int c = i & (C0 - 1);
        float mu  = bnsum[c] * invN;
        float var = bnsq[c] * invN - mu * mu;
        float rs  = rsqrtf(var + BN_EPS);
        float v = (x[i] - mu) * rs * gamma[c] + beta[c];
        x[i] = v > 0.f ? v : expm1f(v);
    }
}

// ---------------- launch ----------------
extern "C" void kernel_launch(void* const* d_in, const int* in_sizes, int n_in,
                              void* d_out, int out_size) {
    const float* data  = (const float*)d_in[0];
    const int*   ei    = (const int*)d_in[1];     // int32! (JAX x64 disabled)
    const float* W0    = (const float*)d_in[2];
    const float* asrc0 = (const float*)d_in[3];
    const float* adst0 = (const float*)d_in[4];
    const float* bias0 = (const float*)d_in[5];
    const float* gam0  = (const float*)d_in[6];
    const float* bet0  = (const float*)d_in[7];
    const float* W1    = (const float*)d_in[8];
    const float* asrc1 = (const float*)d_in[9];
    const float* adst1 = (const float*)d_in[10];
    const float* bias1 = (const float*)d_in[11];
    float* out = (float*)d_out;

    void *ph0, *px1, *ph1, *pa0s, *pa0d, *pa1s, *pa1d;
    void *pbps, *pbpq, *pbnsum, *pbnsq;
    void *pdeg, *pcnt, *pincl, *prowptr, *padj, *pbsum, *pbsums;
    cudaGetSymbolAddress(&ph0,  g_h0);
    cudaGetSymbolAddress(&px1,  g_x1);
    cudaGetSymbolAddress(&ph1,  g_h1);
    cudaGetSymbolAddress(&pa0s, g_a0s);
    cudaGetSymbolAddress(&pa0d, g_a0d);
    cudaGetSymbolAddress(&pa1s, g_a1s);
    cudaGetSymbolAddress(&pa1d, g_a1d);
    cudaGetSymbolAddress(&pbps,   g_bps);
    cudaGetSymbolAddress(&pbpq,   g_bpq);
    cudaGetSymbolAddress(&pbnsum, g_bnsum);
    cudaGetSymbolAddress(&pbnsq,  g_bnsq);
    cudaGetSymbolAddress(&pdeg,   g_deg);
    cudaGetSymbolAddress(&pcnt,   g_cnt);
    cudaGetSymbolAddress(&pincl,  g_incl);
    cudaGetSymbolAddress(&prowptr,g_rowptr);
    cudaGetSymbolAddress(&padj,   g_adj);
    cudaGetSymbolAddress(&pbsum,  g_bsum);
    cudaGetSymbolAddress(&pbsums, g_bsums);

    // ---- CSR build ----
    zero_int_kernel<<<128, 256>>>((int*)pdeg, Nn);
    zero_int_kernel<<<128, 256>>>((int*)pcnt, Nn);
    deg_kernel<<<(ET + 255) / 256, 256>>>(ei, (int*)pdeg);
    scan1_kernel<<<NB1, SCAN_B>>>((int*)pdeg, (int*)pincl, (int*)pbsum);
    scan2_kernel<<<1, 64>>>((int*)pbsum, (int*)pbsums);
    scan3_kernel<<<(Nn + 255) / 256, 256>>>((int*)pincl, (int*)pbsums, (int*)prowptr);
    fill_kernel<<<(ET + 255) / 256, 256>>>(ei, (int*)prowptr, (int*)pcnt, (int*)padj);

    // ---- layer 0 ----
    gemm_kernel<IND, C0, 8><<<(Nn + 7) / 8, C0>>>(data, W0, (float*)ph0, Nn);
    attdot_kernel<C0, 2><<<(Nn + 7) / 8, 256>>>((float*)ph0, asrc0, adst0,
                                                (float*)pa0s, (float*)pa0d);
    agg0_kernel<<<(Nn + 7) / 8, 256>>>((int*)prowptr, (int*)padj,
                                       (float*)pa0s, (float*)pa0d,
                                       (const float4*)ph0, (float4*)px1, bias0);
    bnsum_kernel<<<BN_BLOCKS, C0>>>((float*)px1, (float*)pbps, (float*)pbpq);
    bnred_kernel<<<1, C0>>>((float*)pbps, (float*)pbpq, (float*)pbnsum, (float*)pbnsq);
    bn_elu_kernel<<<2048, 256>>>((float*)px1, (float*)pbnsum, (float*)pbnsq, gam0, bet0);

    // ---- layer 1 ----
    gemm_kernel<C0, OUTD, 8><<<(Nn + 7) / 8, OUTD>>>((float*)px1, W1, (float*)ph1, Nn);
    attdot_kernel<OUTD, 1><<<(Nn + 7) / 8, 256>>>((float*)ph1, asrc1, adst1,
                                                  (float*)pa1s, (float*)pa1d);
    agg1_kernel<<<(Nn + 7) / 8, 256>>>((int*)prowptr, (int*)padj,
                                       (float*)pa1s, (float*)pa1d,
                                       (const float2*)ph1, (float2*)out, bias1);
}

// round 5
// speedup vs baseline: 1.0526x; 1.0526x over previous
#include <cuda_runtime.h>
#include <cstdint>

// ---------------- problem constants ----------------
constexpr int Nn   = 50000;          // nodes
constexpr int Ee   = 800000;         // edges (w/o self loops)
constexpr int ET   = Ee + Nn;        // edges incl. self loops
constexpr int IND  = 128;            // input dim
constexpr int C0   = 128;            // layer0 out channels (2 heads * 64)
constexpr int OUTD = 64;             // layer1 out channels (1 head)
constexpr float NEG_SLOPE = 0.2f;
constexpr float BN_EPS    = 1e-5f;

constexpr int SCAN_B = 1024;
constexpr int NB1    = (Nn + SCAN_B - 1) / SCAN_B;   // 49
constexpr int BN_BLOCKS = 512;

// ---------------- device scratch ----------------
__device__ float4 g_h0[Nn * C0 / 4];     // x@W0
__device__ float4 g_x1[Nn * C0 / 4];     // layer0 out (pre-BN)
__device__ float4 g_h1[Nn * OUTD / 4];   // x1@W1
__device__ float  g_a0s[Nn * 2];
__device__ float  g_a0d[Nn * 2];
__device__ float  g_a1s[Nn];
__device__ float  g_a1d[Nn];
__device__ float  g_bps[BN_BLOCKS * C0]; // BN partial sums
__device__ float  g_bpq[BN_BLOCKS * C0]; // BN partial sum-of-squares
__device__ float  g_bnscale[C0];         // gamma * rsqrt(var+eps)
__device__ float  g_bnshift[C0];         // beta - mu * scale
// CSR
__device__ int    g_deg   [Nn];
__device__ int    g_cnt   [Nn];
__device__ int    g_incl  [Nn];
__device__ int    g_rowptr[Nn + 1];
__device__ int    g_adj   [ET];
__device__ int    g_bsum  [NB1];
__device__ int    g_bsums [NB1];

__device__ __forceinline__ float lrelu(float e) {
    return e > 0.f ? e : NEG_SLOPE * e;
}

// ---------------- zero both CSR counter arrays in one launch ----------------
__global__ void zero2_kernel(int* p0, int* p1, int n) {
    int i = blockIdx.x * blockDim.x + threadIdx.x;
    for (; i < n; i += gridDim.x * blockDim.x) { p0[i] = 0; p1[i] = 0; }
}

// ---------------- CSR build ----------------
__global__ void deg_kernel(const int* __restrict__ ei, int* __restrict__ deg) {
    int i = blockIdx.x * blockDim.x + threadIdx.x;
    if (i >= ET) return;
    int dst = (i < Ee) ? ei[Ee + i] : (i - Ee);
    atomicAdd(&deg[dst], 1);
}

// warp-shuffle inclusive scan: 2 barriers total
__global__ void scan1_kernel(const int* __restrict__ deg,
                             int* __restrict__ incl, int* __restrict__ bsum) {
    __shared__ int wsum[32];
    int tid  = threadIdx.x;
    int lane = tid & 31, wid = tid >> 5;
    int i = blockIdx.x * SCAN_B + tid;
    int v = (i < Nn) ? deg[i] : 0;
#pragma unroll
    for (int off = 1; off < 32; off <<= 1) {
        int t = __shfl_up_sync(0xffffffffu, v, off);
        if (lane >= off) v += t;
    }
    if (lane == 31) wsum[wid] = v;
    __syncthreads();
    if (wid == 0) {
        int w = wsum[lane];
#pragma unroll
        for (int off = 1; off < 32; off <<= 1) {
            int t = __shfl_up_sync(0xffffffffu, w, off);
            if (lane >= off) w += t;
        }
        wsum[lane] = w;
    }
    __syncthreads();
    if (wid > 0) v += wsum[wid - 1];
    if (i < Nn) incl[i] = v;
    if (tid == SCAN_B - 1) bsum[blockIdx.x] = v;
}

__global__ void scan2_kernel(const int* __restrict__ bsum, int* __restrict__ bsums) {
    int lane = threadIdx.x;                  // 64 threads, NB1 <= 64
    int v = (lane < NB1) ? bsum[lane] : 0;
    __shared__ int sh[64];
    sh[lane] = v;
    __syncthreads();
#pragma unroll
    for (int off = 1; off < 64; off <<= 1) {
        int t = (lane >= off) ? sh[lane - off] : 0;
        __syncthreads();
        sh[lane] += t;
        __syncthreads();
    }
    if (lane < NB1) bsums[lane] = sh[lane];
}

__global__ void scan3_kernel(const int* __restrict__ incl,
                             const int* __restrict__ bsums,
                             int* __restrict__ rowptr) {
    int i = blockIdx.x * blockDim.x + threadIdx.x;
    if (i == 0) rowptr[0] = 0;
    if (i >= Nn) return;
    int b = i / SCAN_B;
    int off = (b > 0) ? bsums[b - 1] : 0;
    rowptr[i + 1] = incl[i] + off;
}

__global__ void fill_kernel(const int* __restrict__ ei,
                            const int* __restrict__ rowptr,
                            int* __restrict__ cnt, int* __restrict__ adj) {
    int i = blockIdx.x * blockDim.x + threadIdx.x;
    if (i >= ET) return;
    int src, dst;
    if (i < Ee) { src = ei[i]; dst = ei[Ee + i]; }
    else        { src = dst = i - Ee; }
    int pos = rowptr[dst] + atomicAdd(&cnt[dst], 1);
    adj[pos] = src;
}

// ---------------- GEMM: Y[n, OUTC] = X[n, KD] @ W[KD, OUTC] ----------------
template<int KD, int OUTC, int R>
__global__ void gemm_kernel(const float* __restrict__ X,
                            const float* __restrict__ W,
                            float* __restrict__ Y, int nrows) {
    __shared__ float4 xs4[R * KD / 4];
    float* xs = reinterpret_cast<float*>(xs4);
    const int row0 = blockIdx.x * R;
    const int col  = threadIdx.x;                    // blockDim.x == OUTC

    for (int i = threadIdx.x; i < R * KD; i += OUTC) {
        int r = i / KD, k = i - r * KD;
        int row = row0 + r;
        xs[i] = (row < nrows) ? X[row * KD + k] : 0.f;
    }
    __syncthreads();

    float acc[R];
#pragma unroll
    for (int r = 0; r < R; r++) acc[r] = 0.f;

#pragma unroll 4
    for (int k = 0; k < KD; k += 4) {
        float w0 = W[(k + 0) * OUTC + col];
        float w1 = W[(k + 1) * OUTC + col];
        float w2 = W[(k + 2) * OUTC + col];
        float w3 = W[(k + 3) * OUTC + col];
#pragma unroll
        for (int r = 0; r < R; r++) {
            float4 x4 = xs4[(r * KD + k) >> 2];
            acc[r] += x4.x * w0 + x4.y * w1 + x4.z * w2 + x4.w * w3;
        }
    }
#pragma unroll
    for (int r = 0; r < R; r++) {
        int row = row0 + r;
        if (row < nrows) Y[row * OUTC + col] = acc[r];
    }
}

// -------- GEMM with fused BN(scale/shift)+ELU applied to X while staging -----
template<int KD, int OUTC, int R>
__global__ void gemm_bn_kernel(const float* __restrict__ X,
                               const float* __restrict__ W,
                               float* __restrict__ Y, int nrows,
                               const float* __restrict__ bnscale,
                               const float* __restrict__ bnshift) {
    __shared__ float4 xs4[R * KD / 4];
    float* xs = reinterpret_cast<float*>(xs4);
    const int row0 = blockIdx.x * R;
    const int col  = threadIdx.x;

    for (int i = threadIdx.x; i < R * KD; i += OUTC) {
        int r = i / KD, k = i - r * KD;
        int row = row0 + r;
        float raw = (row < nrows) ? X[row * KD + k] : 0.f;
        float v = raw * bnscale[k] + bnshift[k];
        xs[i] = v > 0.f ? v : expm1f(v);
    }
    __syncthreads();

    float acc[R];
#pragma unroll
    for (int r = 0; r < R; r++) acc[r] = 0.f;

#pragma unroll 4
    for (int k = 0; k < KD; k += 4) {
        float w0 = W[(k + 0) * OUTC + col];
        float w1 = W[(k + 1) * OUTC + col];
        float w2 = W[(k + 2) * OUTC + col];
        float w3 = W[(k + 3) * OUTC + col];
#pragma unroll
        for (int r = 0; r < R; r++) {
            float4 x4 = xs4[(r * KD + k) >> 2];
            acc[r] += x4.x * w0 + x4.y * w1 + x4.z * w2 + x4.w * w3;
        }
    }
#pragma unroll
    for (int r = 0; r < R; r++) {
        int row = row0 + r;
        if (row < nrows) Y[row * OUTC + col] = acc[r];
    }
}

// ---------------- attention dot products (warp per node) ----------------
template<int CH, int H>
__global__ void attdot_kernel(const float* __restrict__ hfeat,
                              const float* __restrict__ att_src,
                              const float* __restrict__ att_dst,
                              float* __restrict__ a_s,
                              float* __restrict__ a_d) {
    int warp = (blockIdx.x * blockDim.x + threadIdx.x) >> 5;
    int lane = threadIdx.x & 31;
    if (warp >= Nn) return;

    float sh[H], dh[H];
#pragma unroll
    for (int h = 0; h < H; h++) { sh[h] = 0.f; dh[h] = 0.f; }

#pragma unroll
    for (int j = 0; j < CH / 32; j++) {
        int c = lane + 32 * j;
        constexpr int CPH = CH / H;
        int h = (32 * j) / CPH;                  // compile-time per j
        float v = hfeat[warp * CH + c];
        sh[h] += v * att_src[c];
        dh[h] += v * att_dst[c];
    }
#pragma unroll
    for (int h = 0; h < H; h++) {
#pragma unroll
        for (int off = 16; off > 0; off >>= 1) {
            sh[h] += __shfl_xor_sync(0xffffffffu, sh[h], off);
            dh[h] += __shfl_xor_sync(0xffffffffu, dh[h], off);
        }
    }
    if (lane == 0) {
#pragma unroll
        for (int h = 0; h < H; h++) {
            a_s[warp * H + h] = sh[h];
            a_d[warp * H + h] = dh[h];
        }
    }
}

// ------- layer0: fused segment softmax + gather-aggregate + bias (warp/node) -
__global__ void agg0_kernel(const int* __restrict__ rowptr,
                            const int* __restrict__ adj,
                            const float* __restrict__ a_s,
                            const float* __restrict__ a_d,
                            const float4* __restrict__ h,
                            float4* __restrict__ out,
                            const float* __restrict__ bias) {
    int node = (blockIdx.x * blockDim.x + threadIdx.x) >> 5;
    int lane = threadIdx.x & 31;
    if (node >= Nn) return;
    const int beg = rowptr[node], end = rowptr[node + 1];
    const float ad0 = a_d[node * 2 + 0];
    const float ad1 = a_d[node * 2 + 1];

    // pass 1: segment max
    float m0 = -1e30f, m1 = -1e30f;
    for (int j = beg + lane; j < end; j += 32) {
        int s = adj[j];
        m0 = fmaxf(m0, lrelu(a_s[s * 2 + 0] + ad0));
        m1 = fmaxf(m1, lrelu(a_s[s * 2 + 1] + ad1));
    }
#pragma unroll
    for (int off = 16; off > 0; off >>= 1) {
        m0 = fmaxf(m0, __shfl_xor_sync(0xffffffffu, m0, off));
        m1 = fmaxf(m1, __shfl_xor_sync(0xffffffffu, m1, off));
    }

    // pass 2: 2x-unrolled serial edge loop (2 gathers in flight)
    const bool hi = (lane >= 16);
    float den0 = 0.f, den1 = 0.f;
    float4 acc = make_float4(0.f, 0.f, 0.f, 0.f);
    int j = beg;
    for (; j + 1 < end; j += 2) {
        int s0 = adj[j], s1 = adj[j + 1];
        float4 v0 = h[(size_t)s0 * (C0 / 4) + lane];
        float4 v1 = h[(size_t)s1 * (C0 / 4) + lane];
        float e00 = __expf(lrelu(a_s[s0 * 2 + 0] + ad0) - m0);
        float e01 = __expf(lrelu(a_s[s0 * 2 + 1] + ad1) - m1);
        float e10 = __expf(lrelu(a_s[s1 * 2 + 0] + ad0) - m0);
        float e11 = __expf(lrelu(a_s[s1 * 2 + 1] + ad1) - m1);
        den0 += e00 + e10; den1 += e01 + e11;
        float sc0 = hi ? e01 : e00;
        float sc1 = hi ? e11 : e10;
        acc.x += v0.x * sc0 + v1.x * sc1;
        acc.y += v0.y * sc0 + v1.y * sc1;
        acc.z += v0.z * sc0 + v1.z * sc1;
        acc.w += v0.w * sc0 + v1.w * sc1;
    }
    if (j < end) {
        int s = adj[j];
        float4 v = h[(size_t)s * (C0 / 4) + lane];
        float ex0 = __expf(lrelu(a_s[s * 2 + 0] + ad0) - m0);
        float ex1 = __expf(lrelu(a_s[s * 2 + 1] + ad1) - m1);
        den0 += ex0; den1 += ex1;
        float sc = hi ? ex1 : ex0;
        acc.x += v.x * sc; acc.y += v.y * sc;
        acc.z += v.z * sc; acc.w += v.w * sc;
    }
    float inv = 1.f / ((hi ? den1 : den0) + 1e-16f);
    int c = lane * 4;
    float4 b4 = *reinterpret_cast<const float4*>(bias + c);
    float4 o;
    o.x = acc.x * inv + b4.x;
    o.y = acc.y * inv + b4.y;
    o.z = acc.z * inv + b4.z;
    o.w = acc.w * inv + b4.w;
    out[(size_t)node * (C0 / 4) + lane] = o;
}

// ------- layer1: fused segment softmax + gather-aggregate + bias -------------
__global__ void agg1_kernel(const int* __restrict__ rowptr,
                            const int* __restrict__ adj,
                            const float* __restrict__ a_s,
                            const float* __restrict__ a_d,
                            const float2* __restrict__ h,
                            float2* __restrict__ out,
                            const float* __restrict__ bias) {
    int node = (blockIdx.x * blockDim.x + threadIdx.x) >> 5;
    int lane = threadIdx.x & 31;
    if (node >= Nn) return;
    const int beg = rowptr[node], end = rowptr[node + 1];
    const float ad = a_d[node];

    float m = -1e30f;
    for (int j = beg + lane; j < end; j += 32) {
        int s = adj[j];
        m = fmaxf(m, lrelu(a_s[s] + ad));
    }
#pragma unroll
    for (int off = 16; off > 0; off >>= 1)
        m = fmaxf(m, __shfl_xor_sync(0xffffffffu, m, off));

    float den = 0.f;
    float2 acc = make_float2(0.f, 0.f);
    int j = beg;
    for (; j + 1 < end; j += 2) {
        int s0 = adj[j], s1 = adj[j + 1];
        float2 v0 = h[(size_t)s0 * (OUTD / 2) + lane];
        float2 v1 = h[(size_t)s1 * (OUTD / 2) + lane];
        float e0 = __expf(lrelu(a_s[s0] + ad) - m);
        float e1 = __expf(lrelu(a_s[s1] + ad) - m);
        den += e0 + e1;
        acc.x += v0.x * e0 + v1.x * e1;
        acc.y += v0.y * e0 + v1.y * e1;
    }
    if (j < end) {
        int s = adj[j];
        float2 v = h[(size_t)s * (OUTD / 2) + lane];
        float ex = __expf(lrelu(a_s[s] + ad) - m);
        den += ex;
        acc.x += v.x * ex; acc.y += v.y * ex;
    }
    float inv = 1.f / (den + 1e-16f);
    int c = lane * 2;
    float2 o;
    o.x = acc.x * inv + bias[c + 0];
    o.y = acc.y * inv + bias[c + 1];
    out[(size_t)node * (OUTD / 2) + lane] = o;
}

// ---------------- BN partial statistics (deterministic) ----------------
__global__ void bnsum_kernel(const float* __restrict__ x,
                             float* __restrict__ bps, float* __restrict__ bpq) {
    int c = threadIdx.x;                         // blockDim.x == 128
    float lsum = 0.f, lsq = 0.f;
    for (int row = blockIdx.x; row < Nn; row += gridDim.x) {
        float v = x[(size_t)row * C0 + c];
        lsum += v;
        lsq  += v * v;
    }
    bps[blockIdx.x * C0 + c] = lsum;
    bpq[blockIdx.x * C0 + c] = lsq;
}

// final reduce -> precomputed scale/shift for the fused gemm1 prologue
__global__ void bnred_kernel(const float* __restrict__ bps,
                             const float* __restrict__ bpq,
                             const float* __restrict__ gamma,
                             const float* __restrict__ beta,
                             float* __restrict__ bnscale,
                             float* __restrict__ bnshift) {
    int c = threadIdx.x;                         // one block of 128 threads
    float s = 0.f, q = 0.f;
    for (int b = 0; b < BN_BLOCKS; b++) {
        s += bps[b * C0 + c];
        q += bpq[b * C0 + c];
    }
    const float invN = 1.0f / (float)Nn;
    float mu  = s * invN;
    float var = q * invN - mu * mu;
    float sc  = gamma[c] * rsqrtf(var + BN_EPS);
    bnscale[c] = sc;
    bnshift[c] = beta[c] - mu * sc;
}

// ---------------- launch ----------------
extern "C" void kernel_launch(void* const* d_in, const int* in_sizes, int n_in,
                              void* d_out, int out_size) {
    const float* data  = (const float*)d_in[0];
    const int*   ei    = (const int*)d_in[1];     // int32 (JAX x64 disabled)
    const float* W0    = (const float*)d_in[2];
    const float* asrc0 = (const float*)d_in[3];
    const float* adst0 = (const float*)d_in[4];
    const float* bias0 = (const float*)d_in[5];
    const float* gam0  = (const float*)d_in[6];
    const float* bet0  = (const float*)d_in[7];
    const float* W1    = (const float*)d_in[8];
    const float* asrc1 = (const float*)d_in[9];
    const float* adst1 = (const float*)d_in[10];
    const float* bias1 = (const float*)d_in[11];
    float* out = (float*)d_out;

    void *ph0, *px1, *ph1, *pa0s, *pa0d, *pa1s, *pa1d;
    void *pbps, *pbpq, *pbnscale, *pbnshift;
    void *pdeg, *pcnt, *pincl, *prowptr, *padj, *pbsum, *pbsums;
    cudaGetSymbolAddress(&ph0,  g_h0);
    cudaGetSymbolAddress(&px1,  g_x1);
    cudaGetSymbolAddress(&ph1,  g_h1);
    cudaGetSymbolAddress(&pa0s, g_a0s);
    cudaGetSymbolAddress(&pa0d, g_a0d);
    cudaGetSymbolAddress(&pa1s, g_a1s);
    cudaGetSymbolAddress(&pa1d, g_a1d);
    cudaGetSymbolAddress(&pbps,     g_bps);
    cudaGetSymbolAddress(&pbpq,     g_bpq);
    cudaGetSymbolAddress(&pbnscale, g_bnscale);
    cudaGetSymbolAddress(&pbnshift, g_bnshift);
    cudaGetSymbolAddress(&pdeg,   g_deg);
    cudaGetSymbolAddress(&pcnt,   g_cnt);
    cudaGetSymbolAddress(&pincl,  g_incl);
    cudaGetSymbolAddress(&prowptr,g_rowptr);
    cudaGetSymbolAddress(&padj,   g_adj);
    cudaGetSymbolAddress(&pbsum,  g_bsum);
    cudaGetSymbolAddress(&pbsums, g_bsums);

    // ---- CSR build ----
    zero2_kernel<<<128, 256>>>((int*)pdeg, (int*)pcnt, Nn);
    deg_kernel<<<(ET + 255) / 256, 256>>>(ei, (int*)pdeg);
    scan1_kernel<<<NB1, SCAN_B>>>((int*)pdeg, (int*)pincl, (int*)pbsum);
    scan2_kernel<<<1, 64>>>((int*)pbsum, (int*)pbsums);
    scan3_kernel<<<(Nn + 255) / 256, 256>>>((int*)pincl, (int*)pbsums, (int*)prowptr);
    fill_kernel<<<(ET + 255) / 256, 256>>>(ei, (int*)prowptr, (int*)pcnt, (int*)padj);

    // ---- layer 0 ----
    gemm_kernel<IND, C0, 8><<<(Nn + 7) / 8, C0>>>(data, W0, (float*)ph0, Nn);
    attdot_kernel<C0, 2><<<(Nn + 7) / 8, 256>>>((float*)ph0, asrc0, adst0,
                                                (float*)pa0s, (float*)pa0d);
    agg0_kernel<<<(Nn + 7) / 8, 256>>>((int*)prowptr, (int*)padj,
                                       (float*)pa0s, (float*)pa0d,
                                       (const float4*)ph0, (float4*)px1, bias0);
    bnsum_kernel<<<BN_BLOCKS, C0>>>((float*)px1, (float*)pbps, (float*)pbpq);
    bnred_kernel<<<1, C0>>>((float*)pbps, (float*)pbpq, gam0, bet0,
                            (float*)pbnscale, (float*)pbnshift);

    // ---- layer 1 (BN+ELU fused into GEMM prologue) ----
    gemm_bn_kernel<C0, OUTD, 8><<<(Nn + 7) / 8, OUTD>>>(
        (float*)px1, W1, (float*)ph1, Nn, (float*)pbnscale, (float*)pbnshift);
    attdot_kernel<OUTD, 1><<<(Nn + 7) / 8, 256>>>((float*)ph1, asrc1, adst1,
                                                  (float*)pa1s, (float*)pa1d);
    agg1_kernel<<<(Nn + 7) / 8, 256>>>((int*)prowptr, (int*)padj,
                                       (float*)pa1s, (float*)pa1d,
                                       (const float2*)ph1, (float2*)out, bias1);
}

// round 6
// speedup vs baseline: 1.1087x; 1.0533x over previous
#include <cuda_runtime.h>
#include <cstdint>

// ---------------- problem constants ----------------
constexpr int Nn   = 50000;          // nodes
constexpr int Ee   = 800000;         // edges (w/o self loops)
constexpr int ET   = Ee + Nn;        // edges incl. self loops
constexpr int IND  = 128;            // input dim
constexpr int C0   = 128;            // layer0 out channels (2 heads * 64)
constexpr int OUTD = 64;             // layer1 out channels (1 head)
constexpr float NEG_SLOPE = 0.2f;
constexpr float BN_EPS    = 1e-5f;

constexpr int SCAN_B = 1024;
constexpr int NB1    = (Nn + SCAN_B - 1) / SCAN_B;   // 49
constexpr int BN_BLOCKS = 512;

// ---------------- device scratch ----------------
__device__ float4 g_h0[Nn * C0 / 4];     // x@W0
__device__ float4 g_x1[Nn * C0 / 4];     // layer0 out (pre-BN)
__device__ float4 g_h1[Nn * OUTD / 4];   // x1@W1
__device__ float  g_a0s[Nn * 2];
__device__ float  g_a0d[Nn * 2];
__device__ float  g_a1s[Nn];
__device__ float  g_a1d[Nn];
__device__ float  g_bps[BN_BLOCKS * C0];
__device__ float  g_bpq[BN_BLOCKS * C0];
__device__ float  g_bnscale[C0];
__device__ float  g_bnshift[C0];
// CSR
__device__ int    g_deg   [Nn];
__device__ int    g_cnt   [Nn];
__device__ int    g_incl  [Nn];
__device__ int    g_rowptr[Nn + 1];
__device__ int    g_adj   [ET];
__device__ int    g_bsum  [NB1];

__device__ __forceinline__ float lrelu(float e) {
    return e > 0.f ? e : NEG_SLOPE * e;
}

// ---------------- zero both CSR counter arrays in one launch ----------------
__global__ void zero2_kernel(int* p0, int* p1, int n) {
    int i = blockIdx.x * blockDim.x + threadIdx.x;
    for (; i < n; i += gridDim.x * blockDim.x) { p0[i] = 0; p1[i] = 0; }
}

// ---------------- CSR build ----------------
__global__ void deg_kernel(const int* __restrict__ ei, int* __restrict__ deg) {
    int i = blockIdx.x * blockDim.x + threadIdx.x;
    if (i >= ET) return;
    int dst = (i < Ee) ? ei[Ee + i] : (i - Ee);
    atomicAdd(&deg[dst], 1);
}

// warp-shuffle inclusive scan per 1024-block
__global__ void scan1_kernel(const int* __restrict__ deg,
                             int* __restrict__ incl, int* __restrict__ bsum) {
    __shared__ int wsum[32];
    int tid  = threadIdx.x;
    int lane = tid & 31, wid = tid >> 5;
    int i = blockIdx.x * SCAN_B + tid;
    int v = (i < Nn) ? deg[i] : 0;
#pragma unroll
    for (int off = 1; off < 32; off <<= 1) {
        int t = __shfl_up_sync(0xffffffffu, v, off);
        if (lane >= off) v += t;
    }
    if (lane == 31) wsum[wid] = v;
    __syncthreads();
    if (wid == 0) {
        int w = wsum[lane];
#pragma unroll
        for (int off = 1; off < 32; off <<= 1) {
            int t = __shfl_up_sync(0xffffffffu, w, off);
            if (lane >= off) w += t;
        }
        wsum[lane] = w;
    }
    __syncthreads();
    if (wid > 0) v += wsum[wid - 1];
    if (i < Nn) incl[i] = v;
    if (tid == SCAN_B - 1) bsum[blockIdx.x] = v;
}

// scan3 with inlined block-sum prefix (smem-staged, replaces scan2)
__global__ void scan3_kernel(const int* __restrict__ incl,
                             const int* __restrict__ bsum,
                             int* __restrict__ rowptr) {
    __shared__ int bs[NB1];
    for (int k = threadIdx.x; k < NB1; k += blockDim.x) bs[k] = bsum[k];
    __syncthreads();
    int i = blockIdx.x * blockDim.x + threadIdx.x;
    if (i == 0) rowptr[0] = 0;
    if (i >= Nn) return;
    int b = i / SCAN_B;
    int off = 0;
    for (int k = 0; k < b; k++) off += bs[k];
    rowptr[i + 1] = incl[i] + off;
}

__global__ void fill_kernel(const int* __restrict__ ei,
                            const int* __restrict__ rowptr,
                            int* __restrict__ cnt, int* __restrict__ adj) {
    int i = blockIdx.x * blockDim.x + threadIdx.x;
    if (i >= ET) return;
    int src, dst;
    if (i < Ee) { src = ei[i]; dst = ei[Ee + i]; }
    else        { src = dst = i - Ee; }
    int pos = rowptr[dst] + atomicAdd(&cnt[dst], 1);
    adj[pos] = src;
}

// ------ GEMM0 + fused attention dots: Y = X@W, a_s/a_d per row (H=2) --------
template<int KD, int OUTC, int R>
__global__ void gemm0_att_kernel(const float* __restrict__ X,
                                 const float* __restrict__ W,
                                 float* __restrict__ Y, int nrows,
                                 const float* __restrict__ att_src,
                                 const float* __restrict__ att_dst,
                                 float* __restrict__ a_s,
                                 float* __restrict__ a_d) {
    __shared__ float4 xs4[R * KD / 4];
    __shared__ float red_s[4][R], red_d[4][R];
    const int row0 = blockIdx.x * R;
    const int col  = threadIdx.x;                 // blockDim.x == OUTC == 128
    const int lane = col & 31, warp = col >> 5;

    const float4* X4 = reinterpret_cast<const float4*>(X);
    for (int i = threadIdx.x; i < R * KD / 4; i += OUTC) {
        int r = i / (KD / 4), k = i - r * (KD / 4);
        int row = row0 + r;
        xs4[i] = (row < nrows) ? X4[(size_t)row * (KD / 4) + k]
                               : make_float4(0.f, 0.f, 0.f, 0.f);
    }
    __syncthreads();

    float acc[R];
#pragma unroll
    for (int r = 0; r < R; r++) acc[r] = 0.f;

#pragma unroll 4
    for (int k = 0; k < KD; k += 4) {
        float w0 = W[(k + 0) * OUTC + col];
        float w1 = W[(k + 1) * OUTC + col];
        float w2 = W[(k + 2) * OUTC + col];
        float w3 = W[(k + 3) * OUTC + col];
#pragma unroll
        for (int r = 0; r < R; r++) {
            float4 x4 = xs4[r * (KD / 4) + (k >> 2)];
            acc[r] += x4.x * w0 + x4.y * w1 + x4.z * w2 + x4.w * w3;
        }
    }

    // store Y + fused attention-dot reduction
    const float asv = att_src[col], adv = att_dst[col];
#pragma unroll
    for (int r = 0; r < R; r++) {
        int row = row0 + r;
        if (row < nrows) Y[(size_t)row * OUTC + col] = acc[r];
        float ps = acc[r] * asv;
        float pd = acc[r] * adv;
#pragma unroll
        for (int off = 16; off > 0; off >>= 1) {
            ps += __shfl_xor_sync(0xffffffffu, ps, off);
            pd += __shfl_xor_sync(0xffffffffu, pd, off);
        }
        if (lane == 0) { red_s[warp][r] = ps; red_d[warp][r] = pd; }
    }
    __syncthreads();
    // warps 0,1 -> head0 ; warps 2,3 -> head1
    if (col < R) {
        int row = row0 + col;
        if (row < nrows) {
            a_s[row * 2 + 0] = red_s[0][col] + red_s[1][col];
            a_d[row * 2 + 0] = red_d[0][col] + red_d[1][col];
        }
    } else if (col >= 32 && col < 32 + R) {
        int r = col - 32, row = row0 + r;
        if (row < nrows) {
            a_s[row * 2 + 1] = red_s[2][r] + red_s[3][r];
            a_d[row * 2 + 1] = red_d[2][r] + red_d[3][r];
        }
    }
}

// -- GEMM1 (BN+ELU fused on X) + fused attention dots (H=1, OUTC=64) ---------
template<int KD, int OUTC, int R>
__global__ void gemm1_bn_att_kernel(const float* __restrict__ X,
                                    const float* __restrict__ W,
                                    float* __restrict__ Y, int nrows,
                                    const float* __restrict__ bnscale,
                                    const float* __restrict__ bnshift,
                                    const float* __restrict__ att_src,
                                    const float* __restrict__ att_dst,
                                    float* __restrict__ a_s,
                                    float* __restrict__ a_d) {
    __shared__ float4 xs4[R * KD / 4];
    __shared__ float red_s[2][R], red_d[2][R];
    const int row0 = blockIdx.x * R;
    const int col  = threadIdx.x;                 // blockDim.x == OUTC == 64
    const int lane = col & 31, warp = col >> 5;

    const float4* X4 = reinterpret_cast<const float4*>(X);
    const float4* sc4 = reinterpret_cast<const float4*>(bnscale);
    const float4* sh4 = reinterpret_cast<const float4*>(bnshift);
    for (int i = threadIdx.x; i < R * KD / 4; i += OUTC) {
        int r = i / (KD / 4), k = i - r * (KD / 4);
        int row = row0 + r;
        float4 raw = (row < nrows) ? X4[(size_t)row * (KD / 4) + k]
                                   : make_float4(0.f, 0.f, 0.f, 0.f);
        float4 sc = sc4[k], sh = sh4[k];
        float4 v;
        v.x = raw.x * sc.x + sh.x;
        v.y = raw.y * sc.y + sh.y;
        v.z = raw.z * sc.z + sh.z;
        v.w = raw.w * sc.w + sh.w;
        v.x = v.x > 0.f ? v.x : expm1f(v.x);
        v.y = v.y > 0.f ? v.y : expm1f(v.y);
        v.z = v.z > 0.f ? v.z : expm1f(v.z);
        v.w = v.w > 0.f ? v.w : expm1f(v.w);
        xs4[i] = v;
    }
    __syncthreads();

    float acc[R];
#pragma unroll
    for (int r = 0; r < R; r++) acc[r] = 0.f;

#pragma unroll 4
    for (int k = 0; k < KD; k += 4) {
        float w0 = W[(k + 0) * OUTC + col];
        float w1 = W[(k + 1) * OUTC + col];
        float w2 = W[(k + 2) * OUTC + col];
        float w3 = W[(k + 3) * OUTC + col];
#pragma unroll
        for (int r = 0; r < R; r++) {
            float4 x4 = xs4[r * (KD / 4) + (k >> 2)];
            acc[r] += x4.x * w0 + x4.y * w1 + x4.z * w2 + x4.w * w3;
        }
    }

    const float asv = att_src[col], adv = att_dst[col];
#pragma unroll
    for (int r = 0; r < R; r++) {
        int row = row0 + r;
        if (row < nrows) Y[(size_t)row * OUTC + col] = acc[r];
        float ps = acc[r] * asv;
        float pd = acc[r] * adv;
#pragma unroll
        for (int off = 16; off > 0; off >>= 1) {
            ps += __shfl_xor_sync(0xffffffffu, ps, off);
            pd += __shfl_xor_sync(0xffffffffu, pd, off);
        }
        if (lane == 0) { red_s[warp][r] = ps; red_d[warp][r] = pd; }
    }
    __syncthreads();
    if (col < R) {
        int row = row0 + col;
        if (row < nrows) {
            a_s[row] = red_s[0][col] + red_s[1][col];
            a_d[row] = red_d[0][col] + red_d[1][col];
        }
    }
}

// ------- layer0: fused segment softmax + gather-aggregate + bias (warp/node) -
__global__ void agg0_kernel(const int* __restrict__ rowptr,
                            const int* __restrict__ adj,
                            const float* __restrict__ a_s,
                            const float* __restrict__ a_d,
                            const float4* __restrict__ h,
                            float4* __restrict__ out,
                            const float* __restrict__ bias) {
    int node = (blockIdx.x * blockDim.x + threadIdx.x) >> 5;
    int lane = threadIdx.x & 31;
    if (node >= Nn) return;
    const int beg = rowptr[node], end = rowptr[node + 1];
    const float ad0 = a_d[node * 2 + 0];
    const float ad1 = a_d[node * 2 + 1];

    float m0 = -1e30f, m1 = -1e30f;
    for (int j = beg + lane; j < end; j += 32) {
        int s = adj[j];
        m0 = fmaxf(m0, lrelu(a_s[s * 2 + 0] + ad0));
        m1 = fmaxf(m1, lrelu(a_s[s * 2 + 1] + ad1));
    }
#pragma unroll
    for (int off = 16; off > 0; off >>= 1) {
        m0 = fmaxf(m0, __shfl_xor_sync(0xffffffffu, m0, off));
        m1 = fmaxf(m1, __shfl_xor_sync(0xffffffffu, m1, off));
    }

    const bool hi = (lane >= 16);
    float den0 = 0.f, den1 = 0.f;
    float4 acc = make_float4(0.f, 0.f, 0.f, 0.f);
    int j = beg;
    for (; j + 1 < end; j += 2) {
        int s0 = adj[j], s1 = adj[j + 1];
        float4 v0 = h[(size_t)s0 * (C0 / 4) + lane];
        float4 v1 = h[(size_t)s1 * (C0 / 4) + lane];
        float e00 = __expf(lrelu(a_s[s0 * 2 + 0] + ad0) - m0);
        float e01 = __expf(lrelu(a_s[s0 * 2 + 1] + ad1) - m1);
        float e10 = __expf(lrelu(a_s[s1 * 2 + 0] + ad0) - m0);
        float e11 = __expf(lrelu(a_s[s1 * 2 + 1] + ad1) - m1);
        den0 += e00 + e10; den1 += e01 + e11;
        float sc0 = hi ? e01 : e00;
        float sc1 = hi ? e11 : e10;
        acc.x += v0.x * sc0 + v1.x * sc1;
        acc.y += v0.y * sc0 + v1.y * sc1;
        acc.z += v0.z * sc0 + v1.z * sc1;
        acc.w += v0.w * sc0 + v1.w * sc1;
    }
    if (j < end) {
        int s = adj[j];
        float4 v = h[(size_t)s * (C0 / 4) + lane];
        float ex0 = __expf(lrelu(a_s[s * 2 + 0] + ad0) - m0);
        float ex1 = __expf(lrelu(a_s[s * 2 + 1] + ad1) - m1);
        den0 += ex0; den1 += ex1;
        float sc = hi ? ex1 : ex0;
        acc.x += v.x * sc; acc.y += v.y * sc;
        acc.z += v.z * sc; acc.w += v.w * sc;
    }
    float inv = 1.f / ((hi ? den1 : den0) + 1e-16f);
    int c = lane * 4;
    float4 b4 = *reinterpret_cast<const float4*>(bias + c);
    float4 o;
    o.x = acc.x * inv + b4.x;
    o.y = acc.y * inv + b4.y;
    o.z = acc.z * inv + b4.z;
    o.w = acc.w * inv + b4.w;
    out[(size_t)node * (C0 / 4) + lane] = o;
}

// ------- layer1: fused segment softmax + gather-aggregate + bias -------------
__global__ void agg1_kernel(const int* __restrict__ rowptr,
                            const int* __restrict__ adj,
                            const float* __restrict__ a_s,
                            const float* __restrict__ a_d,
                            const float2* __restrict__ h,
                            float2* __restrict__ out,
                            const float* __restrict__ bias) {
    int node = (blockIdx.x * blockDim.x + threadIdx.x) >> 5;
    int lane = threadIdx.x & 31;
    if (node >= Nn) return;
    const int beg = rowptr[node], end = rowptr[node + 1];
    const float ad = a_d[node];

    float m = -1e30f;
    for (int j = beg + lane; j < end; j += 32) {
        int s = adj[j];
        m = fmaxf(m, lrelu(a_s[s] + ad));
    }
#pragma unroll
    for (int off = 16; off > 0; off >>= 1)
        m = fmaxf(m, __shfl_xor_sync(0xffffffffu, m, off));

    float den = 0.f;
    float2 acc = make_float2(0.f, 0.f);
    int j = beg;
    for (; j + 1 < end; j += 2) {
        int s0 = adj[j], s1 = adj[j + 1];
        float2 v0 = h[(size_t)s0 * (OUTD / 2) + lane];
        float2 v1 = h[(size_t)s1 * (OUTD / 2) + lane];
        float e0 = __expf(lrelu(a_s[s0] + ad) - m);
        float e1 = __expf(lrelu(a_s[s1] + ad) - m);
        den += e0 + e1;
        acc.x += v0.x * e0 + v1.x * e1;
        acc.y += v0.y * e0 + v1.y * e1;
    }
    if (j < end) {
        int s = adj[j];
        float2 v = h[(size_t)s * (OUTD / 2) + lane];
        float ex = __expf(lrelu(a_s[s] + ad) - m);
        den += ex;
        acc.x += v.x * ex; acc.y += v.y * ex;
    }
    float inv = 1.f / (den + 1e-16f);
    int c = lane * 2;
    float2 o;
    o.x = acc.x * inv + bias[c + 0];
    o.y = acc.y * inv + bias[c + 1];
    out[(size_t)node * (OUTD / 2) + lane] = o;
}

// ---------------- BN partial statistics (deterministic) ----------------
__global__ void bnsum_kernel(const float* __restrict__ x,
                             float* __restrict__ bps, float* __restrict__ bpq) {
    int c = threadIdx.x;                         // blockDim.x == 128
    float lsum = 0.f, lsq = 0.f;
    for (int row = blockIdx.x; row < Nn; row += gridDim.x) {
        float v = x[(size_t)row * C0 + c];
        lsum += v;
        lsq  += v * v;
    }
    bps[blockIdx.x * C0 + c] = lsum;
    bpq[blockIdx.x * C0 + c] = lsq;
}

__global__ void bnred_kernel(const float* __restrict__ bps,
                             const float* __restrict__ bpq,
                             const float* __restrict__ gamma,
                             const float* __restrict__ beta,
                             float* __restrict__ bnscale,
                             float* __restrict__ bnshift) {
    int c = threadIdx.x;                         // one block of 128 threads
    float s = 0.f, q = 0.f;
    for (int b = 0; b < BN_BLOCKS; b++) {
        s += bps[b * C0 + c];
        q += bpq[b * C0 + c];
    }
    const float invN = 1.0f / (float)Nn;
    float mu  = s * invN;
    float var = q * invN - mu * mu;
    float sc  = gamma[c] * rsqrtf(var + BN_EPS);
    bnscale[c] = sc;
    bnshift[c] = beta[c] - mu * sc;
}

// ---------------- launch ----------------
extern "C" void kernel_launch(void* const* d_in, const int* in_sizes, int n_in,
                              void* d_out, int out_size) {
    const float* data  = (const float*)d_in[0];
    const int*   ei    = (const int*)d_in[1];     // int32 (JAX x64 disabled)
    const float* W0    = (const float*)d_in[2];
    const float* asrc0 = (const float*)d_in[3];
    const float* adst0 = (const float*)d_in[4];
    const float* bias0 = (const float*)d_in[5];
    const float* gam0  = (const float*)d_in[6];
    const float* bet0  = (const float*)d_in[7];
    const float* W1    = (const float*)d_in[8];
    const float* asrc1 = (const float*)d_in[9];
    const float* adst1 = (const float*)d_in[10];
    const float* bias1 = (const float*)d_in[11];
    float* out = (float*)d_out;

    void *ph0, *px1, *ph1, *pa0s, *pa0d, *pa1s, *pa1d;
    void *pbps, *pbpq, *pbnscale, *pbnshift;
    void *pdeg, *pcnt, *pincl, *prowptr, *padj, *pbsum;
    cudaGetSymbolAddress(&ph0,  g_h0);
    cudaGetSymbolAddress(&px1,  g_x1);
    cudaGetSymbolAddress(&ph1,  g_h1);
    cudaGetSymbolAddress(&pa0s, g_a0s);
    cudaGetSymbolAddress(&pa0d, g_a0d);
    cudaGetSymbolAddress(&pa1s, g_a1s);
    cudaGetSymbolAddress(&pa1d, g_a1d);
    cudaGetSymbolAddress(&pbps,     g_bps);
    cudaGetSymbolAddress(&pbpq,     g_bpq);
    cudaGetSymbolAddress(&pbnscale, g_bnscale);
    cudaGetSymbolAddress(&pbnshift, g_bnshift);
    cudaGetSymbolAddress(&pdeg,   g_deg);
    cudaGetSymbolAddress(&pcnt,   g_cnt);
    cudaGetSymbolAddress(&pincl,  g_incl);
    cudaGetSymbolAddress(&prowptr,g_rowptr);
    cudaGetSymbolAddress(&padj,   g_adj);
    cudaGetSymbolAddress(&pbsum,  g_bsum);

    // launch order chosen so gemm0 is the 4th launch (ncu capture window)
    zero2_kernel<<<128, 256>>>((int*)pdeg, (int*)pcnt, Nn);                 // 1
    deg_kernel<<<(ET + 255) / 256, 256>>>(ei, (int*)pdeg);                  // 2
    scan1_kernel<<<NB1, SCAN_B>>>((int*)pdeg, (int*)pincl, (int*)pbsum);    // 3
    gemm0_att_kernel<IND, C0, 8><<<(Nn + 7) / 8, C0>>>(                     // 4
        data, W0, (float*)ph0, Nn, asrc0, adst0, (float*)pa0s, (float*)pa0d);
    scan3_kernel<<<(Nn + 255) / 256, 256>>>((int*)pincl, (int*)pbsum,       // 5
                                            (int*)prowptr);
    fill_kernel<<<(ET + 255) / 256, 256>>>(ei, (int*)prowptr, (int*)pcnt,   // 6
                                           (int*)padj);
    agg0_kernel<<<(Nn + 7) / 8, 256>>>((int*)prowptr, (int*)padj,           // 7
                                       (float*)pa0s, (float*)pa0d,
                                       (const float4*)ph0, (float4*)px1, bias0);
    bnsum_kernel<<<BN_BLOCKS, C0>>>((float*)px1, (float*)pbps, (float*)pbpq); // 8
    bnred_kernel<<<1, C0>>>((float*)pbps, (float*)pbpq, gam0, bet0,         // 9
                            (float*)pbnscale, (float*)pbnshift);
    gemm1_bn_att_kernel<C0, OUTD, 8><<<(Nn + 7) / 8, OUTD>>>(               // 10
        (float*)px1, W1, (float*)ph1, Nn,
        (float*)pbnscale, (float*)pbnshift,
        asrc1, adst1, (float*)pa1s, (float*)pa1d);
    agg1_kernel<<<(Nn + 7) / 8, 256>>>((int*)prowptr, (int*)padj,           // 11
                                       (float*)pa1s, (float*)pa1d,
                                       (const float2*)ph1, (float2*)out, bias1);
}

// round 7
// speedup vs baseline: 1.1343x; 1.0231x over previous
#include <cuda_runtime.h>
#include <cstdint>

// ---------------- problem constants ----------------
constexpr int Nn   = 50000;          // nodes
constexpr int Ee   = 800000;         // edges (w/o self loops)
constexpr int ET   = Ee + Nn;        // edges incl. self loops
constexpr int IND  = 128;            // input dim
constexpr int C0   = 128;            // layer0 out channels (2 heads * 64)
constexpr int OUTD = 64;             // layer1 out channels (1 head)
constexpr float NEG_SLOPE = 0.2f;
constexpr float BN_EPS    = 1e-5f;

constexpr int SCAN_B = 1024;
constexpr int NB1    = (Nn + SCAN_B - 1) / SCAN_B;   // 49
constexpr int BN_BLOCKS = 512;

// ---------------- device scratch ----------------
__device__ float4 g_h0[Nn * C0 / 4];     // x@W0
__device__ float4 g_x1[Nn * C0 / 4];     // layer0 out (pre-BN)
__device__ float4 g_h1[Nn * OUTD / 4];   // x1@W1
__device__ float  g_a0s[Nn * 2];
__device__ float  g_a0d[Nn * 2];
__device__ float  g_a1s[Nn];
__device__ float  g_a1d[Nn];
__device__ float  g_bps[BN_BLOCKS * C0];
__device__ float  g_bpq[BN_BLOCKS * C0];
__device__ float4 g_bnscale[C0 / 4];
__device__ float4 g_bnshift[C0 / 4];
// CSR
__device__ int    g_deg   [Nn];
__device__ int    g_cnt   [Nn];
__device__ int    g_incl  [Nn];
__device__ int    g_rowptr[Nn + 1];
__device__ int    g_adj   [ET];
__device__ int    g_bsum  [NB1];

__device__ __forceinline__ float lrelu(float e) {
    return e > 0.f ? e : NEG_SLOPE * e;
}

// ---------------- zero both CSR counter arrays in one launch ----------------
__global__ void zero2_kernel(int* p0, int* p1, int n) {
    int i = blockIdx.x * blockDim.x + threadIdx.x;
    for (; i < n; i += gridDim.x * blockDim.x) { p0[i] = 0; p1[i] = 0; }
}

// ---------------- CSR build ----------------
__global__ void deg_kernel(const int* __restrict__ ei, int* __restrict__ deg) {
    int i = blockIdx.x * blockDim.x + threadIdx.x;
    if (i >= ET) return;
    int dst = (i < Ee) ? ei[Ee + i] : (i - Ee);
    atomicAdd(&deg[dst], 1);
}

__global__ void scan1_kernel(const int* __restrict__ deg,
                             int* __restrict__ incl, int* __restrict__ bsum) {
    __shared__ int wsum[32];
    int tid  = threadIdx.x;
    int lane = tid & 31, wid = tid >> 5;
    int i = blockIdx.x * SCAN_B + tid;
    int v = (i < Nn) ? deg[i] : 0;
#pragma unroll
    for (int off = 1; off < 32; off <<= 1) {
        int t = __shfl_up_sync(0xffffffffu, v, off);
        if (lane >= off) v += t;
    }
    if (lane == 31) wsum[wid] = v;
    __syncthreads();
    if (wid == 0) {
        int w = wsum[lane];
#pragma unroll
        for (int off = 1; off < 32; off <<= 1) {
            int t = __shfl_up_sync(0xffffffffu, w, off);
            if (lane >= off) w += t;
        }
        wsum[lane] = w;
    }
    __syncthreads();
    if (wid > 0) v += wsum[wid - 1];
    if (i < Nn) incl[i] = v;
    if (tid == SCAN_B - 1) bsum[blockIdx.x] = v;
}

__global__ void scan3_kernel(const int* __restrict__ incl,
                             const int* __restrict__ bsum,
                             int* __restrict__ rowptr) {
    __shared__ int bs[NB1];
    for (int k = threadIdx.x; k < NB1; k += blockDim.x) bs[k] = bsum[k];
    __syncthreads();
    int i = blockIdx.x * blockDim.x + threadIdx.x;
    if (i == 0) rowptr[0] = 0;
    if (i >= Nn) return;
    int b = i / SCAN_B;
    int off = 0;
    for (int k = 0; k < b; k++) off += bs[k];
    rowptr[i + 1] = incl[i] + off;
}

__global__ void fill_kernel(const int* __restrict__ ei,
                            const int* __restrict__ rowptr,
                            int* __restrict__ cnt, int* __restrict__ adj) {
    int i = blockIdx.x * blockDim.x + threadIdx.x;
    if (i >= ET) return;
    int src, dst;
    if (i < Ee) { src = ei[i]; dst = ei[Ee + i]; }
    else        { src = dst = i - Ee; }
    int pos = rowptr[dst] + atomicAdd(&cnt[dst], 1);
    adj[pos] = src;
}

// ------ GEMM0 (register-tiled 8x4) + fused attention dots (H=2) -------------
// 256 threads: lane (=tid&31) -> 4 cols, warp (=tid>>5) -> 8 rows. BM=64.
__global__ void gemm0_att_kernel(const float4* __restrict__ X4,
                                 const float4* __restrict__ W4,
                                 float4* __restrict__ Y4, int nrows,
                                 const float4* __restrict__ as4,
                                 const float4* __restrict__ ad4,
                                 float* __restrict__ a_s,
                                 float* __restrict__ a_d) {
    constexpr int BM = 64;
    constexpr int KD = IND;                         // 128
    __shared__ float xs[KD * BM];                   // transposed [k][r], 32 KB
    const int tid  = threadIdx.x;
    const int lane = tid & 31;                      // col group: cols 4*lane
    const int warp = tid >> 5;                      // row group: rows 8*warp
    const int row0 = blockIdx.x * BM;

    // stage X transposed (lanes take consecutive rows -> conflict-free STS)
    for (int i = tid; i < BM * (KD / 4); i += 256) {
        int r  = i & (BM - 1);
        int kk = i >> 6;                            // float4 index in k
        int row = row0 + r;
        float4 v = (row < nrows) ? X4[(size_t)row * (KD / 4) + kk]
                                 : make_float4(0.f, 0.f, 0.f, 0.f);
        xs[(4 * kk + 0) * BM + r] = v.x;
        xs[(4 * kk + 1) * BM + r] = v.y;
        xs[(4 * kk + 2) * BM + r] = v.z;
        xs[(4 * kk + 3) * BM + r] = v.w;
    }
    __syncthreads();

    const float4* xs4 = reinterpret_cast<const float4*>(xs);
    float4 acc[8];
#pragma unroll
    for (int r = 0; r < 8; r++) acc[r] = make_float4(0.f, 0.f, 0.f, 0.f);

#pragma unroll 4
    for (int k = 0; k < KD; k++) {
        float4 w  = W4[k * 32 + lane];              // 4 cols, L1-resident
        float4 xa = xs4[k * (BM / 4) + warp * 2];   // rows 8w+0..3 (broadcast)
        float4 xb = xs4[k * (BM / 4) + warp * 2 + 1]; // rows 8w+4..7
        acc[0].x += xa.x * w.x; acc[0].y += xa.x * w.y; acc[0].z += xa.x * w.z; acc[0].w += xa.x * w.w;
        acc[1].x += xa.y * w.x; acc[1].y += xa.y * w.y; acc[1].z += xa.y * w.z; acc[1].w += xa.y * w.w;
        acc[2].x += xa.z * w.x; acc[2].y += xa.z * w.y; acc[2].z += xa.z * w.z; acc[2].w += xa.z * w.w;
        acc[3].x += xa.w * w.x; acc[3].y += xa.w * w.y; acc[3].z += xa.w * w.z; acc[3].w += xa.w * w.w;
        acc[4].x += xb.x * w.x; acc[4].y += xb.x * w.y; acc[4].z += xb.x * w.z; acc[4].w += xb.x * w.w;
        acc[5].x += xb.y * w.x; acc[5].y += xb.y * w.y; acc[5].z += xb.y * w.z; acc[5].w += xb.y * w.w;
        acc[6].x += xb.z * w.x; acc[6].y += xb.z * w.y; acc[6].z += xb.z * w.z; acc[6].w += xb.z * w.w;
        acc[7].x += xb.w * w.x; acc[7].y += xb.w * w.y; acc[7].z += xb.w * w.z; acc[7].w += xb.w * w.w;
    }

    // epilogue: store Y + fused per-row attention dots (head = lane/16)
    const float4 asv = as4[lane];
    const float4 adv = ad4[lane];
#pragma unroll
    for (int r = 0; r < 8; r++) {
        int row = row0 + warp * 8 + r;
        float4 a = acc[r];
        float ps = a.x * asv.x + a.y * asv.y + a.z * asv.z + a.w * asv.w;
        float pd = a.x * adv.x + a.y * adv.y + a.z * adv.z + a.w * adv.w;
#pragma unroll
        for (int off = 8; off > 0; off >>= 1) {     // reduce within 16-lane half
            ps += __shfl_xor_sync(0xffffffffu, ps, off);
            pd += __shfl_xor_sync(0xffffffffu, pd, off);
        }
        if (row < nrows) {
            Y4[(size_t)row * 32 + lane] = a;
            if (lane == 0)  { a_s[row * 2 + 0] = ps; a_d[row * 2 + 0] = pd; }
            if (lane == 16) { a_s[row * 2 + 1] = ps; a_d[row * 2 + 1] = pd; }
        }
    }
}

// -- GEMM1 (BN+ELU fused on X, register-tiled 4x4) + fused attdot (H=1) ------
// 256 threads: tcol (=tid&15) -> 4 cols, trow (=tid>>4) -> 4 rows. BM=64.
__global__ void gemm1_bn_att_kernel(const float4* __restrict__ X4,
                                    const float4* __restrict__ W4,
                                    float4* __restrict__ Y4, int nrows,
                                    const float4* __restrict__ sc4,
                                    const float4* __restrict__ sh4,
                                    const float4* __restrict__ as4,
                                    const float4* __restrict__ ad4,
                                    float* __restrict__ a_s,
                                    float* __restrict__ a_d) {
    constexpr int BM = 64;
    constexpr int KD = C0;                          // 128
    __shared__ float xs[KD * BM];                   // transposed [k][r], 32 KB
    const int tid  = threadIdx.x;
    const int lane = tid & 31;
    const int tcol = tid & 15;                      // cols 4*tcol
    const int trow = tid >> 4;                      // rows 4*trow (16 groups)
    const int row0 = blockIdx.x * BM;

    // stage X with BN + ELU, transposed
    for (int i = tid; i < BM * (KD / 4); i += 256) {
        int r  = i & (BM - 1);
        int kk = i >> 6;
        int row = row0 + r;
        float4 raw = (row < nrows) ? X4[(size_t)row * (KD / 4) + kk]
                                   : make_float4(0.f, 0.f, 0.f, 0.f);
        float4 sc = sc4[kk], sh = sh4[kk];
        float4 v;
        v.x = raw.x * sc.x + sh.x;
        v.y = raw.y * sc.y + sh.y;
        v.z = raw.z * sc.z + sh.z;
        v.w = raw.w * sc.w + sh.w;
        v.x = v.x > 0.f ? v.x : expm1f(v.x);
        v.y = v.y > 0.f ? v.y : expm1f(v.y);
        v.z = v.z > 0.f ? v.z : expm1f(v.z);
        v.w = v.w > 0.f ? v.w : expm1f(v.w);
        xs[(4 * kk + 0) * BM + r] = v.x;
        xs[(4 * kk + 1) * BM + r] = v.y;
        xs[(4 * kk + 2) * BM + r] = v.z;
        xs[(4 * kk + 3) * BM + r] = v.w;
    }
    __syncthreads();

    const float4* xs4 = reinterpret_cast<const float4*>(xs);
    float4 acc[4];
#pragma unroll
    for (int r = 0; r < 4; r++) acc[r] = make_float4(0.f, 0.f, 0.f, 0.f);

#pragma unroll 4
    for (int k = 0; k < KD; k++) {
        float4 w  = W4[k * 16 + tcol];
        float4 xa = xs4[k * (BM / 4) + trow];       // rows 4*trow..+3
        acc[0].x += xa.x * w.x; acc[0].y += xa.x * w.y; acc[0].z += xa.x * w.z; acc[0].w += xa.x * w.w;
        acc[1].x += xa.y * w.x; acc[1].y += xa.y * w.y; acc[1].z += xa.y * w.z; acc[1].w += xa.y * w.w;
        acc[2].x += xa.z * w.x; acc[2].y += xa.z * w.y; acc[2].z += xa.z * w.z; acc[2].w += xa.z * w.w;
        acc[3].x += xa.w * w.x; acc[3].y += xa.w * w.y; acc[3].z += xa.w * w.z; acc[3].w += xa.w * w.w;
    }

    const float4 asv = as4[tcol];
    const float4 adv = ad4[tcol];
#pragma unroll
    for (int r = 0; r < 4; r++) {
        int row = row0 + trow * 4 + r;
        float4 a = acc[r];
        float ps = a.x * asv.x + a.y * asv.y + a.z * asv.z + a.w * asv.w;
        float pd = a.x * adv.x + a.y * adv.y + a.z * adv.z + a.w * adv.w;
#pragma unroll
        for (int off = 8; off > 0; off >>= 1) {     // reduce within 16-lane half
            ps += __shfl_xor_sync(0xffffffffu, ps, off);
            pd += __shfl_xor_sync(0xffffffffu, pd, off);
        }
        if (row < nrows) {
            Y4[(size_t)row * 16 + tcol] = a;
            if ((lane & 15) == 0) { a_s[row] = ps; a_d[row] = pd; }
        }
    }
}

// ------- layer0: fused segment softmax + gather-aggregate + bias (warp/node) -
__global__ void agg0_kernel(const int* __restrict__ rowptr,
                            const int* __restrict__ adj,
                            const float* __restrict__ a_s,
                            const float* __restrict__ a_d,
                            const float4* __restrict__ h,
                            float4* __restrict__ out,
                            const float* __restrict__ bias) {
    int node = (blockIdx.x * blockDim.x + threadIdx.x) >> 5;
    int lane = threadIdx.x & 31;
    if (node >= Nn) return;
    const int beg = rowptr[node], end = rowptr[node + 1];
    const float ad0 = a_d[node * 2 + 0];
    const float ad1 = a_d[node * 2 + 1];

    float m0 = -1e30f, m1 = -1e30f;
    for (int j = beg + lane; j < end; j += 32) {
        int s = adj[j];
        m0 = fmaxf(m0, lrelu(a_s[s * 2 + 0] + ad0));
        m1 = fmaxf(m1, lrelu(a_s[s * 2 + 1] + ad1));
    }
#pragma unroll
    for (int off = 16; off > 0; off >>= 1) {
        m0 = fmaxf(m0, __shfl_xor_sync(0xffffffffu, m0, off));
        m1 = fmaxf(m1, __shfl_xor_sync(0xffffffffu, m1, off));
    }

    const bool hi = (lane >= 16);
    float den0 = 0.f, den1 = 0.f;
    float4 acc = make_float4(0.f, 0.f, 0.f, 0.f);
    int j = beg;
    for (; j + 1 < end; j += 2) {
        int s0 = adj[j], s1 = adj[j + 1];
        float4 v0 = h[(size_t)s0 * (C0 / 4) + lane];
        float4 v1 = h[(size_t)s1 * (C0 / 4) + lane];
        float e00 = __expf(lrelu(a_s[s0 * 2 + 0] + ad0) - m0);
        float e01 = __expf(lrelu(a_s[s0 * 2 + 1] + ad1) - m1);
        float e10 = __expf(lrelu(a_s[s1 * 2 + 0] + ad0) - m0);
        float e11 = __expf(lrelu(a_s[s1 * 2 + 1] + ad1) - m1);
        den0 += e00 + e10; den1 += e01 + e11;
        float sc0 = hi ? e01 : e00;
        float sc1 = hi ? e11 : e10;
        acc.x += v0.x * sc0 + v1.x * sc1;
        acc.y += v0.y * sc0 + v1.y * sc1;
        acc.z += v0.z * sc0 + v1.z * sc1;
        acc.w += v0.w * sc0 + v1.w * sc1;
    }
    if (j < end) {
        int s = adj[j];
        float4 v = h[(size_t)s * (C0 / 4) + lane];
        float ex0 = __expf(lrelu(a_s[s * 2 + 0] + ad0) - m0);
        float ex1 = __expf(lrelu(a_s[s * 2 + 1] + ad1) - m1);
        den0 += ex0; den1 += ex1;
        float sc = hi ? ex1 : ex0;
        acc.x += v.x * sc; acc.y += v.y * sc;
        acc.z += v.z * sc; acc.w += v.w * sc;
    }
    float inv = 1.f / ((hi ? den1 : den0) + 1e-16f);
    int c = lane * 4;
    float4 b4 = *reinterpret_cast<const float4*>(bias + c);
    float4 o;
    o.x = acc.x * inv + b4.x;
    o.y = acc.y * inv + b4.y;
    o.z = acc.z * inv + b4.z;
    o.w = acc.w * inv + b4.w;
    out[(size_t)node * (C0 / 4) + lane] = o;
}

// ------- layer1: fused segment softmax + gather-aggregate + bias -------------
__global__ void agg1_kernel(const int* __restrict__ rowptr,
                            const int* __restrict__ adj,
                            const float* __restrict__ a_s,
                            const float* __restrict__ a_d,
                            const float2* __restrict__ h,
                            float2* __restrict__ out,
                            const float* __restrict__ bias) {
    int node = (blockIdx.x * blockDim.x + threadIdx.x) >> 5;
    int lane = threadIdx.x & 31;
    if (node >= Nn) return;
    const int beg = rowptr[node], end = rowptr[node + 1];
    const float ad = a_d[node];

    float m = -1e30f;
    for (int j = beg + lane; j < end; j += 32) {
        int s = adj[j];
        m = fmaxf(m, lrelu(a_s[s] + ad));
    }
#pragma unroll
    for (int off = 16; off > 0; off >>= 1)
        m = fmaxf(m, __shfl_xor_sync(0xffffffffu, m, off));

    float den = 0.f;
    float2 acc = make_float2(0.f, 0.f);
    int j = beg;
    for (; j + 1 < end; j += 2) {
        int s0 = adj[j], s1 = adj[j + 1];
        float2 v0 = h[(size_t)s0 * (OUTD / 2) + lane];
        float2 v1 = h[(size_t)s1 * (OUTD / 2) + lane];
        float e0 = __expf(lrelu(a_s[s0] + ad) - m);
        float e1 = __expf(lrelu(a_s[s1] + ad) - m);
        den += e0 + e1;
        acc.x += v0.x * e0 + v1.x * e1;
        acc.y += v0.y * e0 + v1.y * e1;
    }
    if (j < end) {
        int s = adj[j];
        float2 v = h[(size_t)s * (OUTD / 2) + lane];
        float ex = __expf(lrelu(a_s[s] + ad) - m);
        den += ex;
        acc.x += v.x * ex; acc.y += v.y * ex;
    }
    float inv = 1.f / (den + 1e-16f);
    int c = lane * 2;
    float2 o;
    o.x = acc.x * inv + bias[c + 0];
    o.y = acc.y * inv + bias[c + 1];
    out[(size_t)node * (OUTD / 2) + lane] = o;
}

// ---------------- BN partial statistics (deterministic) ----------------
__global__ void bnsum_kernel(const float* __restrict__ x,
                             float* __restrict__ bps, float* __restrict__ bpq) {
    int c = threadIdx.x;                         // blockDim.x == 128
    float lsum = 0.f, lsq = 0.f;
    for (int row = blockIdx.x; row < Nn; row += gridDim.x) {
        float v = x[(size_t)row * C0 + c];
        lsum += v;
        lsq  += v * v;
    }
    bps[blockIdx.x * C0 + c] = lsum;
    bpq[blockIdx.x * C0 + c] = lsq;
}

__global__ void bnred_kernel(const float* __restrict__ bps,
                             const float* __restrict__ bpq,
                             const float* __restrict__ gamma,
                             const float* __restrict__ beta,
                             float* __restrict__ bnscale,
                             float* __restrict__ bnshift) {
    int c = threadIdx.x;                         // one block of 128 threads
    float s = 0.f, q = 0.f;
    for (int b = 0; b < BN_BLOCKS; b++) {
        s += bps[b * C0 + c];
        q += bpq[b * C0 + c];
    }
    const float invN = 1.0f / (float)Nn;
    float mu  = s * invN;
    float var = q * invN - mu * mu;
    float sc  = gamma[c] * rsqrtf(var + BN_EPS);
    bnscale[c] = sc;
    bnshift[c] = beta[c] - mu * sc;
}

// ---------------- launch ----------------
extern "C" void kernel_launch(void* const* d_in, const int* in_sizes, int n_in,
                              void* d_out, int out_size) {
    const float* data  = (const float*)d_in[0];
    const int*   ei    = (const int*)d_in[1];     // int32 (JAX x64 disabled)
    const float* W0    = (const float*)d_in[2];
    const float* asrc0 = (const float*)d_in[3];
    const float* adst0 = (const float*)d_in[4];
    const float* bias0 = (const float*)d_in[5];
    const float* gam0  = (const float*)d_in[6];
    const float* bet0  = (const float*)d_in[7];
    const float* W1    = (const float*)d_in[8];
    const float* asrc1 = (const float*)d_in[9];
    const float* adst1 = (const float*)d_in[10];
    const float* bias1 = (const float*)d_in[11];
    float* out = (float*)d_out;

    void *ph0, *px1, *ph1, *pa0s, *pa0d, *pa1s, *pa1d;
    void *pbps, *pbpq, *pbnscale, *pbnshift;
    void *pdeg, *pcnt, *pincl, *prowptr, *padj, *pbsum;
    cudaGetSymbolAddress(&ph0,  g_h0);
    cudaGetSymbolAddress(&px1,  g_x1);
    cudaGetSymbolAddress(&ph1,  g_h1);
    cudaGetSymbolAddress(&pa0s, g_a0s);
    cudaGetSymbolAddress(&pa0d, g_a0d);
    cudaGetSymbolAddress(&pa1s, g_a1s);
    cudaGetSymbolAddress(&pa1d, g_a1d);
    cudaGetSymbolAddress(&pbps,     g_bps);
    cudaGetSymbolAddress(&pbpq,     g_bpq);
    cudaGetSymbolAddress(&pbnscale, g_bnscale);
    cudaGetSymbolAddress(&pbnshift, g_bnshift);
    cudaGetSymbolAddress(&pdeg,   g_deg);
    cudaGetSymbolAddress(&pcnt,   g_cnt);
    cudaGetSymbolAddress(&pincl,  g_incl);
    cudaGetSymbolAddress(&prowptr,g_rowptr);
    cudaGetSymbolAddress(&padj,   g_adj);
    cudaGetSymbolAddress(&pbsum,  g_bsum);

    // launch order keeps gemm0 as the 4th launch (ncu capture window)
    zero2_kernel<<<128, 256>>>((int*)pdeg, (int*)pcnt, Nn);                 // 1
    deg_kernel<<<(ET + 255) / 256, 256>>>(ei, (int*)pdeg);                  // 2
    scan1_kernel<<<NB1, SCAN_B>>>((int*)pdeg, (int*)pincl, (int*)pbsum);    // 3
    gemm0_att_kernel<<<(Nn + 63) / 64, 256>>>(                              // 4
        (const float4*)data, (const float4*)W0, (float4*)ph0, Nn,
        (const float4*)asrc0, (const float4*)adst0,
        (float*)pa0s, (float*)pa0d);
    scan3_kernel<<<(Nn + 255) / 256, 256>>>((int*)pincl, (int*)pbsum,       // 5
                                            (int*)prowptr);
    fill_kernel<<<(ET + 255) / 256, 256>>>(ei, (int*)prowptr, (int*)pcnt,   // 6
                                           (int*)padj);
    agg0_kernel<<<(Nn + 7) / 8, 256>>>((int*)prowptr, (int*)padj,           // 7
                                       (float*)pa0s, (float*)pa0d,
                                       (const float4*)ph0, (float4*)px1, bias0);
    bnsum_kernel<<<BN_BLOCKS, C0>>>((float*)px1, (float*)pbps, (float*)pbpq); // 8
    bnred_kernel<<<1, C0>>>((float*)pbps, (float*)pbpq, gam0, bet0,         // 9
                            (float*)pbnscale, (float*)pbnshift);
    gemm1_bn_att_kernel<<<(Nn + 63) / 64, 256>>>(                           // 10
        (const float4*)px1, (const float4*)W1, (float4*)ph1, Nn,
        (const float4*)pbnscale, (const float4*)pbnshift,
        (const float4*)asrc1, (const float4*)adst1,
        (float*)pa1s, (float*)pa1d);
    agg1_kernel<<<(Nn + 7) / 8, 256>>>((int*)prowptr, (int*)padj,           // 11
                                       (float*)pa1s, (float*)pa1d,
                                       (const float2*)ph1, (float2*)out, bias1);
}

// round 8
// speedup vs baseline: 1.2077x; 1.0647x over previous
#include <cuda_runtime.h>
#include <cstdint>

// ---------------- problem constants ----------------
constexpr int Nn   = 50000;          // nodes
constexpr int Ee   = 800000;         // edges (w/o self loops)
constexpr int ET   = Ee + Nn;        // edges incl. self loops
constexpr int IND  = 128;            // input dim
constexpr int C0   = 128;            // layer0 out channels (2 heads * 64)
constexpr int OUTD = 64;             // layer1 out channels (1 head)
constexpr float NEG_SLOPE = 0.2f;
constexpr float BN_EPS    = 1e-5f;

constexpr int SCAN_B = 1024;
constexpr int NB1    = (Nn + SCAN_B - 1) / SCAN_B;   // 49
constexpr int BN_BLOCKS = 512;

// ---------------- device scratch ----------------
__device__ float4 g_h0[Nn * C0 / 4];     // x@W0
__device__ float4 g_x1[Nn * C0 / 4];     // layer0 out (pre-BN)
__device__ float4 g_h1[Nn * OUTD / 4];   // x1@W1
__device__ float  g_a0s[Nn * 2];
__device__ float  g_a0d[Nn * 2];
__device__ float  g_a1s[Nn];
__device__ float  g_a1d[Nn];
__device__ float  g_bps[BN_BLOCKS * C0];
__device__ float  g_bpq[BN_BLOCKS * C0];
__device__ float4 g_bnscale[C0 / 4];
__device__ float4 g_bnshift[C0 / 4];
// CSR
__device__ int    g_deg   [Nn];
__device__ int    g_cnt   [Nn];
__device__ int    g_incl  [Nn];
__device__ int    g_rowptr[Nn + 1];
__device__ int    g_adj   [ET];
__device__ int    g_bsum  [NB1];

__device__ __forceinline__ float lrelu(float e) {
    return e > 0.f ? e : NEG_SLOPE * e;
}

__device__ __forceinline__ uint32_t f2tf32(float f) {
    uint32_t u;
    asm("cvt.rna.tf32.f32 %0, %1;" : "=r"(u) : "f"(f));
    return u;
}

__device__ __forceinline__ void mma_tf32(float4& c, const uint32_t* a, const uint32_t* b) {
    asm volatile(
        "mma.sync.aligned.m16n8k8.row.col.f32.tf32.tf32.f32 "
        "{%0,%1,%2,%3}, {%4,%5,%6,%7}, {%8,%9}, {%0,%1,%2,%3};"
        : "+f"(c.x), "+f"(c.y), "+f"(c.z), "+f"(c.w)
        : "r"(a[0]), "r"(a[1]), "r"(a[2]), "r"(a[3]), "r"(b[0]), "r"(b[1]));
}

// ---------------- zero both CSR counter arrays in one launch ----------------
__global__ void zero2_kernel(int* p0, int* p1, int n) {
    int i = blockIdx.x * blockDim.x + threadIdx.x;
    for (; i < n; i += gridDim.x * blockDim.x) { p0[i] = 0; p1[i] = 0; }
}

// ---------------- CSR build ----------------
__global__ void deg_kernel(const int* __restrict__ ei, int* __restrict__ deg) {
    int i = blockIdx.x * blockDim.x + threadIdx.x;
    if (i >= ET) return;
    int dst = (i < Ee) ? ei[Ee + i] : (i - Ee);
    atomicAdd(&deg[dst], 1);
}

__global__ void scan1_kernel(const int* __restrict__ deg,
                             int* __restrict__ incl, int* __restrict__ bsum) {
    __shared__ int wsum[32];
    int tid  = threadIdx.x;
    int lane = tid & 31, wid = tid >> 5;
    int i = blockIdx.x * SCAN_B + tid;
    int v = (i < Nn) ? deg[i] : 0;
#pragma unroll
    for (int off = 1; off < 32; off <<= 1) {
        int t = __shfl_up_sync(0xffffffffu, v, off);
        if (lane >= off) v += t;
    }
    if (lane == 31) wsum[wid] = v;
    __syncthreads();
    if (wid == 0) {
        int w = wsum[lane];
#pragma unroll
        for (int off = 1; off < 32; off <<= 1) {
            int t = __shfl_up_sync(0xffffffffu, w, off);
            if (lane >= off) w += t;
        }
        wsum[lane] = w;
    }
    __syncthreads();
    if (wid > 0) v += wsum[wid - 1];
    if (i < Nn) incl[i] = v;
    if (tid == SCAN_B - 1) bsum[blockIdx.x] = v;
}

__global__ void scan3_kernel(const int* __restrict__ incl,
                             const int* __restrict__ bsum,
                             int* __restrict__ rowptr) {
    __shared__ int bs[NB1];
    for (int k = threadIdx.x; k < NB1; k += blockDim.x) bs[k] = bsum[k];
    __syncthreads();
    int i = blockIdx.x * blockDim.x + threadIdx.x;
    if (i == 0) rowptr[0] = 0;
    if (i >= Nn) return;
    int b = i / SCAN_B;
    int off = 0;
    for (int k = 0; k < b; k++) off += bs[k];
    rowptr[i + 1] = incl[i] + off;
}

__global__ void fill_kernel(const int* __restrict__ ei,
                            const int* __restrict__ rowptr,
                            int* __restrict__ cnt, int* __restrict__ adj) {
    int i = blockIdx.x * blockDim.x + threadIdx.x;
    if (i >= ET) return;
    int src, dst;
    if (i < Ee) { src = ei[i]; dst = ei[Ee + i]; }
    else        { src = dst = i - Ee; }
    int pos = rowptr[dst] + atomicAdd(&cnt[dst], 1);
    adj[pos] = src;
}

// ------ GEMM0 via tf32x3 tensor cores + fused attention dots (H=2) ----------
// 256 threads = 8 warps in 2(m) x 4(n): warp tile m32 x n32, block 64 x 128.
constexpr int XS = 132;                 // padded smem stride (floats)
__global__ void gemm0_tf32_att_kernel(const float4* __restrict__ X4,
                                      const float* __restrict__ W,
                                      float* __restrict__ Y, int nrows,
                                      const float* __restrict__ att_src,
                                      const float* __restrict__ att_dst,
                                      float* __restrict__ a_s,
                                      float* __restrict__ a_d) {
    __shared__ float xs[64 * XS];                    // 33.8 KB
    __shared__ float reds[8][32], redd[8][32];
    const int tid  = threadIdx.x;
    const int lane = tid & 31;
    const int warp = tid >> 5;
    const int warp_m = warp >> 2;                    // 0..1 -> rows 32*wm
    const int warp_n = warp & 3;                     // 0..3 -> cols 32*wn
    const int row0 = blockIdx.x * 64;

    // stage X tile (64 x 128), padded row stride; float4 stores are 16B-aligned
    for (int i = tid; i < 64 * 32; i += 256) {
        int r = i >> 5, kk = i & 31;
        int row = row0 + r;
        float4 v = (row < nrows) ? X4[(size_t)row * 32 + kk]
                                 : make_float4(0.f, 0.f, 0.f, 0.f);
        *reinterpret_cast<float4*>(&xs[r * XS + kk * 4]) = v;
    }
    __syncthreads();

    float4 acc[2][4];
#pragma unroll
    for (int mt = 0; mt < 2; mt++)
#pragma unroll
        for (int nt = 0; nt < 4; nt++) acc[mt][nt] = make_float4(0.f, 0.f, 0.f, 0.f);

    const int mrow = warp_m * 32;
    const int ncol = warp_n * 32;
    const int lq = lane >> 2;                        // group id 0..7
    const int lr = lane & 3;                         // id in group 0..3

    for (int kt = 0; kt < 16; kt++) {
        const int k0 = kt * 8;
        // A fragments (m16k8), hi/lo split
        uint32_t ahi[2][4], alo[2][4];
#pragma unroll
        for (int mt = 0; mt < 2; mt++) {
            int rb = mrow + mt * 16 + lq;
            float f0 = xs[rb * XS + k0 + lr];
            float f1 = xs[(rb + 8) * XS + k0 + lr];
            float f2 = xs[rb * XS + k0 + lr + 4];
            float f3 = xs[(rb + 8) * XS + k0 + lr + 4];
            ahi[mt][0] = f2tf32(f0); alo[mt][0] = f2tf32(f0 - __uint_as_float(ahi[mt][0]));
            ahi[mt][1] = f2tf32(f1); alo[mt][1] = f2tf32(f1 - __uint_as_float(ahi[mt][1]));
            ahi[mt][2] = f2tf32(f2); alo[mt][2] = f2tf32(f2 - __uint_as_float(ahi[mt][2]));
            ahi[mt][3] = f2tf32(f3); alo[mt][3] = f2tf32(f3 - __uint_as_float(ahi[mt][3]));
        }
        // B fragments (k8n8), hi/lo split; W row-major [k][128], L1-resident
        uint32_t bhi[4][2], blo[4][2];
#pragma unroll
        for (int nt = 0; nt < 4; nt++) {
            int col = ncol + nt * 8 + lq;
            float f0 = W[(k0 + lr) * 128 + col];
            float f1 = W[(k0 + lr + 4) * 128 + col];
            bhi[nt][0] = f2tf32(f0); blo[nt][0] = f2tf32(f0 - __uint_as_float(bhi[nt][0]));
            bhi[nt][1] = f2tf32(f1); blo[nt][1] = f2tf32(f1 - __uint_as_float(bhi[nt][1]));
        }
        // tf32x3: lo terms first, hi*hi last
#pragma unroll
        for (int mt = 0; mt < 2; mt++)
#pragma unroll
            for (int nt = 0; nt < 4; nt++) {
                mma_tf32(acc[mt][nt], alo[mt], bhi[nt]);
                mma_tf32(acc[mt][nt], ahi[mt], blo[nt]);
                mma_tf32(acc[mt][nt], ahi[mt], bhi[nt]);
            }
    }

    // epilogue: store Y + fused attention dots
    float ps[2][2] = {{0.f, 0.f}, {0.f, 0.f}};
    float pd[2][2] = {{0.f, 0.f}, {0.f, 0.f}};
#pragma unroll
    for (int mt = 0; mt < 2; mt++) {
#pragma unroll
        for (int nt = 0; nt < 4; nt++) {
            float4 a = acc[mt][nt];
            int col = ncol + nt * 8 + lr * 2;
            int row = row0 + mrow + mt * 16 + lq;
            float s0 = att_src[col], s1 = att_src[col + 1];
            float d0 = att_dst[col], d1 = att_dst[col + 1];
            ps[mt][0] += a.x * s0 + a.y * s1;
            pd[mt][0] += a.x * d0 + a.y * d1;
            ps[mt][1] += a.z * s0 + a.w * s1;
            pd[mt][1] += a.z * d0 + a.w * d1;
            if (row < nrows)
                *reinterpret_cast<float2*>(&Y[(size_t)row * 128 + col]) = make_float2(a.x, a.y);
            if (row + 8 < nrows)
                *reinterpret_cast<float2*>(&Y[(size_t)(row + 8) * 128 + col]) = make_float2(a.z, a.w);
        }
#pragma unroll
        for (int half = 0; half < 2; half++) {
#pragma unroll
            for (int off = 1; off <= 2; off <<= 1) {
                ps[mt][half] += __shfl_xor_sync(0xffffffffu, ps[mt][half], off);
                pd[mt][half] += __shfl_xor_sync(0xffffffffu, pd[mt][half], off);
            }
            if (lr == 0) {
                reds[warp][mt * 16 + half * 8 + lq] = ps[mt][half];
                redd[warp][mt * 16 + half * 8 + lq] = pd[mt][half];
            }
        }
    }
    __syncthreads();
    if (tid < 128) {
        int r = tid & 63, h = tid >> 6;
        int grow = row0 + r;
        if (grow < nrows) {
            int wm = r >> 5, rl = r & 31;
            int wA = wm * 4 + 2 * h;
            a_s[grow * 2 + h] = reds[wA][rl] + reds[wA + 1][rl];
            a_d[grow * 2 + h] = redd[wA][rl] + redd[wA + 1][rl];
        }
    }
}

// -- GEMM1 (BN+ELU fused on X, register-tiled 4x4) + fused attdot (H=1) ------
__global__ void gemm1_bn_att_kernel(const float4* __restrict__ X4,
                                    const float4* __restrict__ W4,
                                    float4* __restrict__ Y4, int nrows,
                                    const float4* __restrict__ sc4,
                                    const float4* __restrict__ sh4,
                                    const float4* __restrict__ as4,
                                    const float4* __restrict__ ad4,
                                    float* __restrict__ a_s,
                                    float* __restrict__ a_d) {
    constexpr int BM = 64;
    constexpr int KD = C0;                          // 128
    __shared__ float xsm[KD * BM];                  // transposed [k][r], 32 KB
    const int tid  = threadIdx.x;
    const int lane = tid & 31;
    const int tcol = tid & 15;
    const int trow = tid >> 4;
    const int row0 = blockIdx.x * BM;

    for (int i = tid; i < BM * (KD / 4); i += 256) {
        int r  = i & (BM - 1);
        int kk = i >> 6;
        int row = row0 + r;
        float4 raw = (row < nrows) ? X4[(size_t)row * (KD / 4) + kk]
                                   : make_float4(0.f, 0.f, 0.f, 0.f);
        float4 sc = sc4[kk], sh = sh4[kk];
        float4 v;
        v.x = raw.x * sc.x + sh.x;
        v.y = raw.y * sc.y + sh.y;
        v.z = raw.z * sc.z + sh.z;
        v.w = raw.w * sc.w + sh.w;
        v.x = v.x > 0.f ? v.x : expm1f(v.x);
        v.y = v.y > 0.f ? v.y : expm1f(v.y);
        v.z = v.z > 0.f ? v.z : expm1f(v.z);
        v.w = v.w > 0.f ? v.w : expm1f(v.w);
        xsm[(4 * kk + 0) * BM + r] = v.x;
        xsm[(4 * kk + 1) * BM + r] = v.y;
        xsm[(4 * kk + 2) * BM + r] = v.z;
        xsm[(4 * kk + 3) * BM + r] = v.w;
    }
    __syncthreads();

    const float4* xs4 = reinterpret_cast<const float4*>(xsm);
    float4 acc[4];
#pragma unroll
    for (int r = 0; r < 4; r++) acc[r] = make_float4(0.f, 0.f, 0.f, 0.f);

#pragma unroll 4
    for (int k = 0; k < KD; k++) {
        float4 w  = W4[k * 16 + tcol];
        float4 xa = xs4[k * (BM / 4) + trow];
        acc[0].x += xa.x * w.x; acc[0].y += xa.x * w.y; acc[0].z += xa.x * w.z; acc[0].w += xa.x * w.w;
        acc[1].x += xa.y * w.x; acc[1].y += xa.y * w.y; acc[1].z += xa.y * w.z; acc[1].w += xa.y * w.w;
        acc[2].x += xa.z * w.x; acc[2].y += xa.z * w.y; acc[2].z += xa.z * w.z; acc[2].w += xa.z * w.w;
        acc[3].x += xa.w * w.x; acc[3].y += xa.w * w.y; acc[3].z += xa.w * w.z; acc[3].w += xa.w * w.w;
    }

    const float4 asv = as4[tcol];
    const float4 adv = ad4[tcol];
#pragma unroll
    for (int r = 0; r < 4; r++) {
        int row = row0 + trow * 4 + r;
        float4 a = acc[r];
        float ps = a.x * asv.x + a.y * asv.y + a.z * asv.z + a.w * asv.w;
        float pd = a.x * adv.x + a.y * adv.y + a.z * adv.z + a.w * adv.w;
#pragma unroll
        for (int off = 8; off > 0; off >>= 1) {
            ps += __shfl_xor_sync(0xffffffffu, ps, off);
            pd += __shfl_xor_sync(0xffffffffu, pd, off);
        }
        if (row < nrows) {
            Y4[(size_t)row * 16 + tcol] = a;
            if ((lane & 15) == 0) { a_s[row] = ps; a_d[row] = pd; }
        }
    }
}

// ------- layer0: fused segment softmax + gather-aggregate + bias (warp/node) -
__global__ void agg0_kernel(const int* __restrict__ rowptr,
                            const int* __restrict__ adj,
                            const float* __restrict__ a_s,
                            const float* __restrict__ a_d,
                            const float4* __restrict__ h,
                            float4* __restrict__ out,
                            const float* __restrict__ bias) {
    int node = (blockIdx.x * blockDim.x + threadIdx.x) >> 5;
    int lane = threadIdx.x & 31;
    if (node >= Nn) return;
    const int beg = rowptr[node], end = rowptr[node + 1];
    const float ad0 = a_d[node * 2 + 0];
    const float ad1 = a_d[node * 2 + 1];

    float m0 = -1e30f, m1 = -1e30f;
    for (int j = beg + lane; j < end; j += 32) {
        int s = adj[j];
        m0 = fmaxf(m0, lrelu(a_s[s * 2 + 0] + ad0));
        m1 = fmaxf(m1, lrelu(a_s[s * 2 + 1] + ad1));
    }
#pragma unroll
    for (int off = 16; off > 0; off >>= 1) {
        m0 = fmaxf(m0, __shfl_xor_sync(0xffffffffu, m0, off));
        m1 = fmaxf(m1, __shfl_xor_sync(0xffffffffu, m1, off));
    }

    const bool hi = (lane >= 16);
    float den0 = 0.f, den1 = 0.f;
    float4 acc = make_float4(0.f, 0.f, 0.f, 0.f);
    int j = beg;
    for (; j + 1 < end; j += 2) {
        int s0 = adj[j], s1 = adj[j + 1];
        float4 v0 = h[(size_t)s0 * (C0 / 4) + lane];
        float4 v1 = h[(size_t)s1 * (C0 / 4) + lane];
        float e00 = __expf(lrelu(a_s[s0 * 2 + 0] + ad0) - m0);
        float e01 = __expf(lrelu(a_s[s0 * 2 + 1] + ad1) - m1);
        float e10 = __expf(lrelu(a_s[s1 * 2 + 0] + ad0) - m0);
        float e11 = __expf(lrelu(a_s[s1 * 2 + 1] + ad1) - m1);
        den0 += e00 + e10; den1 += e01 + e11;
        float sc0 = hi ? e01 : e00;
        float sc1 = hi ? e11 : e10;
        acc.x += v0.x * sc0 + v1.x * sc1;
        acc.y += v0.y * sc0 + v1.y * sc1;
        acc.z += v0.z * sc0 + v1.z * sc1;
        acc.w += v0.w * sc0 + v1.w * sc1;
    }
    if (j < end) {
        int s = adj[j];
        float4 v = h[(size_t)s * (C0 / 4) + lane];
        float ex0 = __expf(lrelu(a_s[s * 2 + 0] + ad0) - m0);
        float ex1 = __expf(lrelu(a_s[s * 2 + 1] + ad1) - m1);
        den0 += ex0; den1 += ex1;
        float sc = hi ? ex1 : ex0;
        acc.x += v.x * sc; acc.y += v.y * sc;
        acc.z += v.z * sc; acc.w += v.w * sc;
    }
    float inv = 1.f / ((hi ? den1 : den0) + 1e-16f);
    int c = lane * 4;
    float4 b4 = *reinterpret_cast<const float4*>(bias + c);
    float4 o;
    o.x = acc.x * inv + b4.x;
    o.y = acc.y * inv + b4.y;
    o.z = acc.z * inv + b4.z;
    o.w = acc.w * inv + b4.w;
    out[(size_t)node * (C0 / 4) + lane] = o;
}

// ------- layer1: fused segment softmax + gather-aggregate + bias -------------
__global__ void agg1_kernel(const int* __restrict__ rowptr,
                            const int* __restrict__ adj,
                            const float* __restrict__ a_s,
                            const float* __restrict__ a_d,
                            const float2* __restrict__ h,
                            float2* __restrict__ out,
                            const float* __restrict__ bias) {
    int node = (blockIdx.x * blockDim.x + threadIdx.x) >> 5;
    int lane = threadIdx.x & 31;
    if (node >= Nn) return;
    const int beg = rowptr[node], end = rowptr[node + 1];
    const float ad = a_d[node];

    float m = -1e30f;
    for (int j = beg + lane; j < end; j += 32) {
        int s = adj[j];
        m = fmaxf(m, lrelu(a_s[s] + ad));
    }
#pragma unroll
    for (int off = 16; off > 0; off >>= 1)
        m = fmaxf(m, __shfl_xor_sync(0xffffffffu, m, off));

    float den = 0.f;
    float2 acc = make_float2(0.f, 0.f);
    int j = beg;
    for (; j + 1 < end; j += 2) {
        int s0 = adj[j], s1 = adj[j + 1];
        float2 v0 = h[(size_t)s0 * (OUTD / 2) + lane];
        float2 v1 = h[(size_t)s1 * (OUTD / 2) + lane];
        float e0 = __expf(lrelu(a_s[s0] + ad) - m);
        float e1 = __expf(lrelu(a_s[s1] + ad) - m);
        den += e0 + e1;
        acc.x += v0.x * e0 + v1.x * e1;
        acc.y += v0.y * e0 + v1.y * e1;
    }
    if (j < end) {
        int s = adj[j];
        float2 v = h[(size_t)s * (OUTD / 2) + lane];
        float ex = __expf(lrelu(a_s[s] + ad) - m);
        den += ex;
        acc.x += v.x * ex; acc.y += v.y * ex;
    }
    float inv = 1.f / (den + 1e-16f);
    int c = lane * 2;
    float2 o;
    o.x = acc.x * inv + bias[c + 0];
    o.y = acc.y * inv + bias[c + 1];
    out[(size_t)node * (OUTD / 2) + lane] = o;
}

// ---------------- BN partial statistics (deterministic) ----------------
__global__ void bnsum_kernel(const float* __restrict__ x,
                             float* __restrict__ bps, float* __restrict__ bpq) {
    int c = threadIdx.x;                         // blockDim.x == 128
    float lsum = 0.f, lsq = 0.f;
    for (int row = blockIdx.x; row < Nn; row += gridDim.x) {
        float v = x[(size_t)row * C0 + c];
        lsum += v;
        lsq  += v * v;
    }
    bps[blockIdx.x * C0 + c] = lsum;
    bpq[blockIdx.x * C0 + c] = lsq;
}

__global__ void bnred_kernel(const float* __restrict__ bps,
                             const float* __restrict__ bpq,
                             const float* __restrict__ gamma,
                             const float* __restrict__ beta,
                             float* __restrict__ bnscale,
                             float* __restrict__ bnshift) {
    int c = threadIdx.x;                         // one block of 128 threads
    float s = 0.f, q = 0.f;
    for (int b = 0; b < BN_BLOCKS; b++) {
        s += bps[b * C0 + c];
        q += bpq[b * C0 + c];
    }
    const float invN = 1.0f / (float)Nn;
    float mu  = s * invN;
    float var = q * invN - mu * mu;
    float sc  = gamma[c] * rsqrtf(var + BN_EPS);
    bnscale[c] = sc;
    bnshift[c] = beta[c] - mu * sc;
}

// ---------------- launch ----------------
extern "C" void kernel_launch(void* const* d_in, const int* in_sizes, int n_in,
                              void* d_out, int out_size) {
    const float* data  = (const float*)d_in[0];
    const int*   ei    = (const int*)d_in[1];     // int32 (JAX x64 disabled)
    const float* W0    = (const float*)d_in[2];
    const float* asrc0 = (const float*)d_in[3];
    const float* adst0 = (const float*)d_in[4];
    const float* bias0 = (const float*)d_in[5];
    const float* gam0  = (const float*)d_in[6];
    const float* bet0  = (const float*)d_in[7];
    const float* W1    = (const float*)d_in[8];
    const float* asrc1 = (const float*)d_in[9];
    const float* adst1 = (const float*)d_in[10];
    const float* bias1 = (const float*)d_in[11];
    float* out = (float*)d_out;

    void *ph0, *px1, *ph1, *pa0s, *pa0d, *pa1s, *pa1d;
    void *pbps, *pbpq, *pbnscale, *pbnshift;
    void *pdeg, *pcnt, *pincl, *prowptr, *padj, *pbsum;
    cudaGetSymbolAddress(&ph0,  g_h0);
    cudaGetSymbolAddress(&px1,  g_x1);
    cudaGetSymbolAddress(&ph1,  g_h1);
    cudaGetSymbolAddress(&pa0s, g_a0s);
    cudaGetSymbolAddress(&pa0d, g_a0d);
    cudaGetSymbolAddress(&pa1s, g_a1s);
    cudaGetSymbolAddress(&pa1d, g_a1d);
    cudaGetSymbolAddress(&pbps,     g_bps);
    cudaGetSymbolAddress(&pbpq,     g_bpq);
    cudaGetSymbolAddress(&pbnscale, g_bnscale);
    cudaGetSymbolAddress(&pbnshift, g_bnshift);
    cudaGetSymbolAddress(&pdeg,   g_deg);
    cudaGetSymbolAddress(&pcnt,   g_cnt);
    cudaGetSymbolAddress(&pincl,  g_incl);
    cudaGetSymbolAddress(&prowptr,g_rowptr);
    cudaGetSymbolAddress(&padj,   g_adj);
    cudaGetSymbolAddress(&pbsum,  g_bsum);

    // launch order keeps gemm0 as the 4th launch (ncu capture window)
    zero2_kernel<<<128, 256>>>((int*)pdeg, (int*)pcnt, Nn);                 // 1
    deg_kernel<<<(ET + 255) / 256, 256>>>(ei, (int*)pdeg);                  // 2
    scan1_kernel<<<NB1, SCAN_B>>>((int*)pdeg, (int*)pincl, (int*)pbsum);    // 3
    gemm0_tf32_att_kernel<<<(Nn + 63) / 64, 256>>>(                         // 4
        (const float4*)data, W0, (float*)ph0, Nn,
        asrc0, adst0, (float*)pa0s, (float*)pa0d);
    scan3_kernel<<<(Nn + 255) / 256, 256>>>((int*)pincl, (int*)pbsum,       // 5
                                            (int*)prowptr);
    fill_kernel<<<(ET + 255) / 256, 256>>>(ei, (int*)prowptr, (int*)pcnt,   // 6
                                           (int*)padj);
    agg0_kernel<<<(Nn + 7) / 8, 256>>>((int*)prowptr, (int*)padj,           // 7
                                       (float*)pa0s, (float*)pa0d,
                                       (const float4*)ph0, (float4*)px1, bias0);
    bnsum_kernel<<<BN_BLOCKS, C0>>>((float*)px1, (float*)pbps, (float*)pbpq); // 8
    bnred_kernel<<<1, C0>>>((float*)pbps, (float*)pbpq, gam0, bet0,         // 9
                            (float*)pbnscale, (float*)pbnshift);
    gemm1_bn_att_kernel<<<(Nn + 63) / 64, 256>>>(                           // 10
        (const float4*)px1, (const float4*)W1, (float4*)ph1, Nn,
        (const float4*)pbnscale, (const float4*)pbnshift,
        (const float4*)asrc1, (const float4*)adst1,
        (float*)pa1s, (float*)pa1d);
    agg1_kernel<<<(Nn + 7) / 8, 256>>>((int*)prowptr, (int*)padj,           // 11
                                       (float*)pa1s, (float*)pa1d,
                                       (const float2*)ph1, (float2*)out, bias1);
}

// round 9
// speedup vs baseline: 1.2614x; 1.0444x over previous
#include <cuda_runtime.h>
#include <cstdint>

// ---------------- problem constants ----------------
constexpr int Nn   = 50000;          // nodes
constexpr int Ee   = 800000;         // edges (w/o self loops)
constexpr int ET   = Ee + Nn;        // edges incl. self loops
constexpr int IND  = 128;            // input dim
constexpr int C0   = 128;            // layer0 out channels (2 heads * 64)
constexpr int OUTD = 64;             // layer1 out channels (1 head)
constexpr float NEG_SLOPE = 0.2f;
constexpr float BN_EPS    = 1e-5f;

constexpr int SCAN_B = 1024;
constexpr int NB1    = (Nn + SCAN_B - 1) / SCAN_B;   // 49
constexpr int BN_BLOCKS = 512;

constexpr int APAD = 68;             // padded A-pack row stride (uint4)
constexpr int GEMM_SMEM = 64 * APAD * 16;   // 69632 bytes

// ---------------- device scratch ----------------
__device__ float4 g_h0[Nn * C0 / 4];     // x@W0
__device__ float4 g_x1[Nn * C0 / 4];     // layer0 out (pre-BN)
__device__ float4 g_h1[Nn * OUTD / 4];   // x1@W1
__device__ float  g_a0s[Nn * 2];
__device__ float  g_a0d[Nn * 2];
__device__ float  g_a1s[Nn];
__device__ float  g_a1d[Nn];
__device__ float  g_bps[BN_BLOCKS * C0];
__device__ float  g_bpq[BN_BLOCKS * C0];
__device__ float4 g_bnscale[C0 / 4];
__device__ float4 g_bnshift[C0 / 4];
__device__ uint4  g_w0pack[128 * 16 * 4];    // [c][kt][lr] {hi0,hi1,lo0,lo1}
__device__ uint4  g_w1pack[64 * 32 * 4];     // same for W1 (kt<32 unused top half)
// CSR
__device__ int    g_deg   [Nn];
__device__ int    g_cnt   [Nn];
__device__ int    g_incl  [Nn];
__device__ int    g_rowptr[Nn + 1];
__device__ int    g_adj   [ET];
__device__ int    g_bsum  [NB1];

__device__ __forceinline__ float lrelu(float e) {
    return e > 0.f ? e : NEG_SLOPE * e;
}

__device__ __forceinline__ uint32_t f2tf32(float f) {
    uint32_t u;
    asm("cvt.rna.tf32.f32 %0, %1;" : "=r"(u) : "f"(f));
    return u;
}

__device__ __forceinline__ void mma_tf32(float4& c, const uint32_t* a, const uint32_t* b) {
    asm volatile(
        "mma.sync.aligned.m16n8k8.row.col.f32.tf32.tf32.f32 "
        "{%0,%1,%2,%3}, {%4,%5,%6,%7}, {%8,%9}, {%0,%1,%2,%3};"
        : "+f"(c.x), "+f"(c.y), "+f"(c.z), "+f"(c.w)
        : "r"(a[0]), "r"(a[1]), "r"(a[2]), "r"(a[3]), "r"(b[0]), "r"(b[1]));
}

// ---------------- zero both CSR counter arrays in one launch ----------------
__global__ void zero2_kernel(int* p0, int* p1, int n) {
    int i = blockIdx.x * blockDim.x + threadIdx.x;
    for (; i < n; i += gridDim.x * blockDim.x) { p0[i] = 0; p1[i] = 0; }
}

// -------- pre-split W0/W1 into tf32 hi/lo fragment-ordered uint4 ------------
__global__ void wsplit_kernel(const float* __restrict__ W0,
                              const float* __restrict__ W1,
                              uint4* __restrict__ w0p, uint4* __restrict__ w1p) {
    int idx = blockIdx.x * blockDim.x + threadIdx.x;
    if (idx < 128 * 64) {                       // W0: c<128, 16 kt, 4 lr
        int c = idx >> 6, t = idx & 63;
        int kt = t >> 2, lr = t & 3, k0 = 8 * kt;
        float f0 = W0[(k0 + lr) * 128 + c];
        float f1 = W0[(k0 + lr + 4) * 128 + c];
        uint32_t h0 = f2tf32(f0), h1 = f2tf32(f1);
        uint32_t l0 = f2tf32(f0 - __uint_as_float(h0));
        uint32_t l1 = f2tf32(f1 - __uint_as_float(h1));
        w0p[idx] = make_uint4(h0, h1, l0, l1);
    } else if (idx < 128 * 64 + 64 * 64) {      // W1: c<64, 16 kt, 4 lr
        int j = idx - 128 * 64;
        int c = j >> 6, t = j & 63;
        int kt = t >> 2, lr = t & 3, k0 = 8 * kt;
        float f0 = W1[(k0 + lr) * 64 + c];
        float f1 = W1[(k0 + lr + 4) * 64 + c];
        uint32_t h0 = f2tf32(f0), h1 = f2tf32(f1);
        uint32_t l0 = f2tf32(f0 - __uint_as_float(h0));
        uint32_t l1 = f2tf32(f1 - __uint_as_float(h1));
        w1p[c * 64 + kt * 4 + lr] = make_uint4(h0, h1, l0, l1);
    }
}

// ---------------- CSR build ----------------
__global__ void deg_kernel(const int* __restrict__ ei, int* __restrict__ deg) {
    int i = blockIdx.x * blockDim.x + threadIdx.x;
    if (i >= ET) return;
    int dst = (i < Ee) ? ei[Ee + i] : (i - Ee);
    atomicAdd(&deg[dst], 1);
}

__global__ void scan1_kernel(const int* __restrict__ deg,
                             int* __restrict__ incl, int* __restrict__ bsum) {
    __shared__ int wsum[32];
    int tid  = threadIdx.x;
    int lane = tid & 31, wid = tid >> 5;
    int i = blockIdx.x * SCAN_B + tid;
    int v = (i < Nn) ? deg[i] : 0;
#pragma unroll
    for (int off = 1; off < 32; off <<= 1) {
        int t = __shfl_up_sync(0xffffffffu, v, off);
        if (lane >= off) v += t;
    }
    if (lane == 31) wsum[wid] = v;
    __syncthreads();
    if (wid == 0) {
        int w = wsum[lane];
#pragma unroll
        for (int off = 1; off < 32; off <<= 1) {
            int t = __shfl_up_sync(0xffffffffu, w, off);
            if (lane >= off) w += t;
        }
        wsum[lane] = w;
    }
    __syncthreads();
    if (wid > 0) v += wsum[wid - 1];
    if (i < Nn) incl[i] = v;
    if (tid == SCAN_B - 1) bsum[blockIdx.x] = v;
}

__global__ void scan3_kernel(const int* __restrict__ incl,
                             const int* __restrict__ bsum,
                             int* __restrict__ rowptr) {
    __shared__ int bs[NB1];
    for (int k = threadIdx.x; k < NB1; k += blockDim.x) bs[k] = bsum[k];
    __syncthreads();
    int i = blockIdx.x * blockDim.x + threadIdx.x;
    if (i == 0) rowptr[0] = 0;
    if (i >= Nn) return;
    int b = i / SCAN_B;
    int off = 0;
    for (int k = 0; k < b; k++) off += bs[k];
    rowptr[i + 1] = incl[i] + off;
}

__global__ void fill_kernel(const int* __restrict__ ei,
                            const int* __restrict__ rowptr,
                            int* __restrict__ cnt, int* __restrict__ adj) {
    int i = blockIdx.x * blockDim.x + threadIdx.x;
    if (i >= ET) return;
    int src, dst;
    if (i < Ee) { src = ei[i]; dst = ei[Ee + i]; }
    else        { src = dst = i - Ee; }
    int pos = rowptr[dst] + atomicAdd(&cnt[dst], 1);
    adj[pos] = src;
}

// ------ GEMM0 tf32x3, pre-split operands + fused attention dots (H=2) -------
// 256 threads = 8 warps in 2(m) x 4(n): warp tile m32 x n32, block 64 x 128.
__global__ void gemm0_tf32_att_kernel(const float4* __restrict__ X4,
                                      const uint4* __restrict__ Wp,
                                      float* __restrict__ Y, int nrows,
                                      const float* __restrict__ att_src,
                                      const float* __restrict__ att_dst,
                                      float* __restrict__ a_s,
                                      float* __restrict__ a_d) {
    extern __shared__ uint4 apack[];                 // [64][APAD]
    __shared__ float reds[8][32], redd[8][32];
    uint32_t* aw = reinterpret_cast<uint32_t*>(apack);
    const int tid  = threadIdx.x;
    const int lane = tid & 31;
    const int warp = tid >> 5;
    const int warp_m = warp >> 2;
    const int warp_n = warp & 3;
    const int row0 = blockIdx.x * 64;

    // stage X, split to tf32 hi/lo in fragment-ordered packed layout
    for (int i = tid; i < 64 * 32; i += 256) {
        int r = i >> 5, kk = i & 31;
        int row = row0 + r;
        float4 v = (row < nrows) ? X4[(size_t)row * 32 + kk]
                                 : make_float4(0.f, 0.f, 0.f, 0.f);
        int kt = kk >> 1, half = kk & 1;
        int base = (r * APAD + kt * 4) * 4;
        float f[4] = {v.x, v.y, v.z, v.w};
#pragma unroll
        for (int j = 0; j < 4; j++) {
            uint32_t h = f2tf32(f[j]);
            uint32_t l = f2tf32(f[j] - __uint_as_float(h));
            aw[base + j * 4 + half]     = h;
            aw[base + j * 4 + 2 + half] = l;
        }
    }
    __syncthreads();

    float4 acc[2][4];
#pragma unroll
    for (int mt = 0; mt < 2; mt++)
#pragma unroll
        for (int nt = 0; nt < 4; nt++) acc[mt][nt] = make_float4(0.f, 0.f, 0.f, 0.f);

    const int mrow = warp_m * 32;
    const int ncol = warp_n * 32;
    const int lq = lane >> 2;
    const int lr = lane & 3;

#pragma unroll 4
    for (int kt = 0; kt < 16; kt++) {
        uint32_t ahi[2][4], alo[2][4];
#pragma unroll
        for (int mt = 0; mt < 2; mt++) {
            int rb = mrow + mt * 16 + lq;
            uint4 A0 = apack[rb * APAD + kt * 4 + lr];
            uint4 A1 = apack[(rb + 8) * APAD + kt * 4 + lr];
            ahi[mt][0] = A0.x; ahi[mt][1] = A1.x; ahi[mt][2] = A0.y; ahi[mt][3] = A1.y;
            alo[mt][0] = A0.z; alo[mt][1] = A1.z; alo[mt][2] = A0.w; alo[mt][3] = A1.w;
        }
#pragma unroll
        for (int nt = 0; nt < 4; nt++) {
            int col = ncol + nt * 8 + lq;
            uint4 B = Wp[col * 64 + kt * 4 + lr];
            uint32_t bhi[2] = {B.x, B.y};
            uint32_t blo[2] = {B.z, B.w};
#pragma unroll
            for (int mt = 0; mt < 2; mt++) {
                mma_tf32(acc[mt][nt], alo[mt], bhi);
                mma_tf32(acc[mt][nt], ahi[mt], blo);
                mma_tf32(acc[mt][nt], ahi[mt], bhi);
            }
        }
    }

    // epilogue: store Y + fused attention dots
    float ps[2][2] = {{0.f, 0.f}, {0.f, 0.f}};
    float pd[2][2] = {{0.f, 0.f}, {0.f, 0.f}};
#pragma unroll
    for (int mt = 0; mt < 2; mt++) {
#pragma unroll
        for (int nt = 0; nt < 4; nt++) {
            float4 a = acc[mt][nt];
            int col = ncol + nt * 8 + lr * 2;
            int row = row0 + mrow + mt * 16 + lq;
            float s0 = att_src[col], s1 = att_src[col + 1];
            float d0 = att_dst[col], d1 = att_dst[col + 1];
            ps[mt][0] += a.x * s0 + a.y * s1;
            pd[mt][0] += a.x * d0 + a.y * d1;
            ps[mt][1] += a.z * s0 + a.w * s1;
            pd[mt][1] += a.z * d0 + a.w * d1;
            if (row < nrows)
                *reinterpret_cast<float2*>(&Y[(size_t)row * 128 + col]) = make_float2(a.x, a.y);
            if (row + 8 < nrows)
                *reinterpret_cast<float2*>(&Y[(size_t)(row + 8) * 128 + col]) = make_float2(a.z, a.w);
        }
#pragma unroll
        for (int half = 0; half < 2; half++) {
#pragma unroll
            for (int off = 1; off <= 2; off <<= 1) {
                ps[mt][half] += __shfl_xor_sync(0xffffffffu, ps[mt][half], off);
                pd[mt][half] += __shfl_xor_sync(0xffffffffu, pd[mt][half], off);
            }
            if (lr == 0) {
                reds[warp][mt * 16 + half * 8 + lq] = ps[mt][half];
                redd[warp][mt * 16 + half * 8 + lq] = pd[mt][half];
            }
        }
    }
    __syncthreads();
    if (tid < 128) {
        int r = tid & 63, h = tid >> 6;
        int grow = row0 + r;
        if (grow < nrows) {
            int wm = r >> 5, rl = r & 31;
            int wA = wm * 4 + 2 * h;
            a_s[grow * 2 + h] = reds[wA][rl] + reds[wA + 1][rl];
            a_d[grow * 2 + h] = redd[wA][rl] + redd[wA + 1][rl];
        }
    }
}

// -- GEMM1 tf32x3 (BN+ELU fused on X) + fused attdot (H=1, 64 cols) ----------
// 256 threads = 8 warps in 4(m) x 2(n): warp tile m16 x n32, block 64 x 64.
__global__ void gemm1_tf32_att_kernel(const float4* __restrict__ X4,
                                      const uint4* __restrict__ Wp,
                                      float* __restrict__ Y, int nrows,
                                      const float4* __restrict__ sc4,
                                      const float4* __restrict__ sh4,
                                      const float* __restrict__ att_src,
                                      const float* __restrict__ att_dst,
                                      float* __restrict__ a_s,
                                      float* __restrict__ a_d) {
    extern __shared__ uint4 apack[];                 // [64][APAD]
    __shared__ float reds[8][16], redd[8][16];
    uint32_t* aw = reinterpret_cast<uint32_t*>(apack);
    const int tid  = threadIdx.x;
    const int lane = tid & 31;
    const int warp = tid >> 5;
    const int warp_m = warp >> 1;                    // 0..3 -> rows 16*wm
    const int warp_n = warp & 1;                     // 0..1 -> cols 32*wn
    const int row0 = blockIdx.x * 64;

    // stage X with BN+ELU, split to tf32 hi/lo packed
    for (int i = tid; i < 64 * 32; i += 256) {
        int r = i >> 5, kk = i & 31;
        int row = row0 + r;
        float4 raw = (row < nrows) ? X4[(size_t)row * 32 + kk]
                                   : make_float4(0.f, 0.f, 0.f, 0.f);
        float4 sc = sc4[kk], sh = sh4[kk];
        float f[4];
        f[0] = raw.x * sc.x + sh.x;
        f[1] = raw.y * sc.y + sh.y;
        f[2] = raw.z * sc.z + sh.z;
        f[3] = raw.w * sc.w + sh.w;
#pragma unroll
        for (int j = 0; j < 4; j++) f[j] = f[j] > 0.f ? f[j] : expm1f(f[j]);
        int kt = kk >> 1, half = kk & 1;
        int base = (r * APAD + kt * 4) * 4;
#pragma unroll
        for (int j = 0; j < 4; j++) {
            uint32_t h = f2tf32(f[j]);
            uint32_t l = f2tf32(f[j] - __uint_as_float(h));
            aw[base + j * 4 + half]     = h;
            aw[base + j * 4 + 2 + half] = l;
        }
    }
    __syncthreads();

    float4 acc[4];
#pragma unroll
    for (int nt = 0; nt < 4; nt++) acc[nt] = make_float4(0.f, 0.f, 0.f, 0.f);

    const int mrow = warp_m * 16;
    const int ncol = warp_n * 32;
    const int lq = lane >> 2;
    const int lr = lane & 3;

#pragma unroll 4
    for (int kt = 0; kt < 16; kt++) {
        uint4 A0 = apack[(mrow + lq) * APAD + kt * 4 + lr];
        uint4 A1 = apack[(mrow + 8 + lq) * APAD + kt * 4 + lr];
        uint32_t ahi[4] = {A0.x, A1.x, A0.y, A1.y};
        uint32_t alo[4] = {A0.z, A1.z, A0.w, A1.w};
#pragma unroll
        for (int nt = 0; nt < 4; nt++) {
            int col = ncol + nt * 8 + lq;
            uint4 B = Wp[col * 64 + kt * 4 + lr];
            uint32_t bhi[2] = {B.x, B.y};
            uint32_t blo[2] = {B.z, B.w};
            mma_tf32(acc[nt], alo, bhi);
            mma_tf32(acc[nt], ahi, blo);
            mma_tf32(acc[nt], ahi, bhi);
        }
    }

    // epilogue
    float ps[2] = {0.f, 0.f}, pd[2] = {0.f, 0.f};
#pragma unroll
    for (int nt = 0; nt < 4; nt++) {
        float4 a = acc[nt];
        int col = ncol + nt * 8 + lr * 2;
        int row = row0 + mrow + lq;
        float s0 = att_src[col], s1 = att_src[col + 1];
        float d0 = att_dst[col], d1 = att_dst[col + 1];
        ps[0] += a.x * s0 + a.y * s1;
        pd[0] += a.x * d0 + a.y * d1;
        ps[1] += a.z * s0 + a.w * s1;
        pd[1] += a.z * d0 + a.w * d1;
        if (row < nrows)
            *reinterpret_cast<float2*>(&Y[(size_t)row * 64 + col]) = make_float2(a.x, a.y);
        if (row + 8 < nrows)
            *reinterpret_cast<float2*>(&Y[(size_t)(row + 8) * 64 + col]) = make_float2(a.z, a.w);
    }
#pragma unroll
    for (int half = 0; half < 2; half++) {
#pragma unroll
        for (int off = 1; off <= 2; off <<= 1) {
            ps[half] += __shfl_xor_sync(0xffffffffu, ps[half], off);
            pd[half] += __shfl_xor_sync(0xffffffffu, pd[half], off);
        }
        if (lr == 0) {
            reds[warp][half * 8 + lq] = ps[half];
            redd[warp][half * 8 + lq] = pd[half];
        }
    }
    __syncthreads();
    if (tid < 64) {
        int grow = row0 + tid;
        if (grow < nrows) {
            int wm = tid >> 4, rl = tid & 15;
            a_s[grow] = reds[wm * 2][rl] + reds[wm * 2 + 1][rl];
            a_d[grow] = redd[wm * 2][rl] + redd[wm * 2 + 1][rl];
        }
    }
}

// ------- layer0: fused segment softmax + gather-aggregate + bias (warp/node) -
__global__ void agg0_kernel(const int* __restrict__ rowptr,
                            const int* __restrict__ adj,
                            const float* __restrict__ a_s,
                            const float* __restrict__ a_d,
                            const float4* __restrict__ h,
                            float4* __restrict__ out,
                            const float* __restrict__ bias) {
    int node = (blockIdx.x * blockDim.x + threadIdx.x) >> 5;
    int lane = threadIdx.x & 31;
    if (node >= Nn) return;
    const int beg = rowptr[node], end = rowptr[node + 1];
    const float ad0 = a_d[node * 2 + 0];
    const float ad1 = a_d[node * 2 + 1];

    float m0 = -1e30f, m1 = -1e30f;
    for (int j = beg + lane; j < end; j += 32) {
        int s = adj[j];
        m0 = fmaxf(m0, lrelu(a_s[s * 2 + 0] + ad0));
        m1 = fmaxf(m1, lrelu(a_s[s * 2 + 1] + ad1));
    }
#pragma unroll
    for (int off = 16; off > 0; off >>= 1) {
        m0 = fmaxf(m0, __shfl_xor_sync(0xffffffffu, m0, off));
        m1 = fmaxf(m1, __shfl_xor_sync(0xffffffffu, m1, off));
    }

    const bool hi = (lane >= 16);
    float den0 = 0.f, den1 = 0.f;
    float4 acc = make_float4(0.f, 0.f, 0.f, 0.f);
    int j = beg;
    for (; j + 1 < end; j += 2) {
        int s0 = adj[j], s1 = adj[j + 1];
        float4 v0 = h[(size_t)s0 * (C0 / 4) + lane];
        float4 v1 = h[(size_t)s1 * (C0 / 4) + lane];
        float e00 = __expf(lrelu(a_s[s0 * 2 + 0] + ad0) - m0);
        float e01 = __expf(lrelu(a_s[s0 * 2 + 1] + ad1) - m1);
        float e10 = __expf(lrelu(a_s[s1 * 2 + 0] + ad0) - m0);
        float e11 = __expf(lrelu(a_s[s1 * 2 + 1] + ad1) - m1);
        den0 += e00 + e10; den1 += e01 + e11;
        float sc0 = hi ? e01 : e00;
        float sc1 = hi ? e11 : e10;
        acc.x += v0.x * sc0 + v1.x * sc1;
        acc.y += v0.y * sc0 + v1.y * sc1;
        acc.z += v0.z * sc0 + v1.z * sc1;
        acc.w += v0.w * sc0 + v1.w * sc1;
    }
    if (j < end) {
        int s = adj[j];
        float4 v = h[(size_t)s * (C0 / 4) + lane];
        float ex0 = __expf(lrelu(a_s[s * 2 + 0] + ad0) - m0);
        float ex1 = __expf(lrelu(a_s[s * 2 + 1] + ad1) - m1);
        den0 += ex0; den1 += ex1;
        float sc = hi ? ex1 : ex0;
        acc.x += v.x * sc; acc.y += v.y * sc;
        acc.z += v.z * sc; acc.w += v.w * sc;
    }
    float inv = 1.f / ((hi ? den1 : den0) + 1e-16f);
    int c = lane * 4;
    float4 b4 = *reinterpret_cast<const float4*>(bias + c);
    float4 o;
    o.x = acc.x * inv + b4.x;
    o.y = acc.y * inv + b4.y;
    o.z = acc.z * inv + b4.z;
    o.w = acc.w * inv + b4.w;
    out[(size_t)node * (C0 / 4) + lane] = o;
}

// ------- layer1: fused segment softmax + gather-aggregate + bias -------------
__global__ void agg1_kernel(const int* __restrict__ rowptr,
                            const int* __restrict__ adj,
                            const float* __restrict__ a_s,
                            const float* __restrict__ a_d,
                            const float2* __restrict__ h,
                            float2* __restrict__ out,
                            const float* __restrict__ bias) {
    int node = (blockIdx.x * blockDim.x + threadIdx.x) >> 5;
    int lane = threadIdx.x & 31;
    if (node >= Nn) return;
    const int beg = rowptr[node], end = rowptr[node + 1];
    const float ad = a_d[node];

    float m = -1e30f;
    for (int j = beg + lane; j < end; j += 32) {
        int s = adj[j];
        m = fmaxf(m, lrelu(a_s[s] + ad));
    }
#pragma unroll
    for (int off = 16; off > 0; off >>= 1)
        m = fmaxf(m, __shfl_xor_sync(0xffffffffu, m, off));

    float den = 0.f;
    float2 acc = make_float2(0.f, 0.f);
    int j = beg;
    for (; j + 1 < end; j += 2) {
        int s0 = adj[j], s1 = adj[j + 1];
        float2 v0 = h[(size_t)s0 * (OUTD / 2) + lane];
        float2 v1 = h[(size_t)s1 * (OUTD / 2) + lane];
        float e0 = __expf(lrelu(a_s[s0] + ad) - m);
        float e1 = __expf(lrelu(a_s[s1] + ad) - m);
        den += e0 + e1;
        acc.x += v0.x * e0 + v1.x * e1;
        acc.y += v0.y * e0 + v1.y * e1;
    }
    if (j < end) {
        int s = adj[j];
        float2 v = h[(size_t)s * (OUTD / 2) + lane];
        float ex = __expf(lrelu(a_s[s] + ad) - m);
        den += ex;
        acc.x += v.x * ex; acc.y += v.y * ex;
    }
    float inv = 1.f / (den + 1e-16f);
    int c = lane * 2;
    float2 o;
    o.x = acc.x * inv + bias[c + 0];
    o.y = acc.y * inv + bias[c + 1];
    out[(size_t)node * (OUTD / 2) + lane] = o;
}

// ---------------- BN partial statistics (deterministic) ----------------
__global__ void bnsum_kernel(const float* __restrict__ x,
                             float* __restrict__ bps, float* __restrict__ bpq) {
    int c = threadIdx.x;                         // blockDim.x == 128
    float lsum = 0.f, lsq = 0.f;
    for (int row = blockIdx.x; row < Nn; row += gridDim.x) {
        float v = x[(size_t)row * C0 + c];
        lsum += v;
        lsq  += v * v;
    }
    bps[blockIdx.x * C0 + c] = lsum;
    bpq[blockIdx.x * C0 + c] = lsq;
}

__global__ void bnred_kernel(const float* __restrict__ bps,
                             const float* __restrict__ bpq,
                             const float* __restrict__ gamma,
                             const float* __restrict__ beta,
                             float* __restrict__ bnscale,
                             float* __restrict__ bnshift) {
    int c = threadIdx.x;                         // one block of 128 threads
    float s = 0.f, q = 0.f;
    for (int b = 0; b < BN_BLOCKS; b++) {
        s += bps[b * C0 + c];
        q += bpq[b * C0 + c];
    }
    const float invN = 1.0f / (float)Nn;
    float mu  = s * invN;
    float var = q * invN - mu * mu;
    float sc  = gamma[c] * rsqrtf(var + BN_EPS);
    bnscale[c] = sc;
    bnshift[c] = beta[c] - mu * sc;
}

// ---------------- launch ----------------
extern "C" void kernel_launch(void* const* d_in, const int* in_sizes, int n_in,
                              void* d_out, int out_size) {
    const float* data  = (const float*)d_in[0];
    const int*   ei    = (const int*)d_in[1];     // int32 (JAX x64 disabled)
    const float* W0    = (const float*)d_in[2];
    const float* asrc0 = (const float*)d_in[3];
    const float* adst0 = (const float*)d_in[4];
    const float* bias0 = (const float*)d_in[5];
    const float* gam0  = (const float*)d_in[6];
    const float* bet0  = (const float*)d_in[7];
    const float* W1    = (const float*)d_in[8];
    const float* asrc1 = (const float*)d_in[9];
    const float* adst1 = (const float*)d_in[10];
    const float* bias1 = (const float*)d_in[11];
    float* out = (float*)d_out;

    void *ph0, *px1, *ph1, *pa0s, *pa0d, *pa1s, *pa1d;
    void *pbps, *pbpq, *pbnscale, *pbnshift, *pw0p, *pw1p;
    void *pdeg, *pcnt, *pincl, *prowptr, *padj, *pbsum;
    cudaGetSymbolAddress(&ph0,  g_h0);
    cudaGetSymbolAddress(&px1,  g_x1);
    cudaGetSymbolAddress(&ph1,  g_h1);
    cudaGetSymbolAddress(&pa0s, g_a0s);
    cudaGetSymbolAddress(&pa0d, g_a0d);
    cudaGetSymbolAddress(&pa1s, g_a1s);
    cudaGetSymbolAddress(&pa1d, g_a1d);
    cudaGetSymbolAddress(&pbps,     g_bps);
    cudaGetSymbolAddress(&pbpq,     g_bpq);
    cudaGetSymbolAddress(&pbnscale, g_bnscale);
    cudaGetSymbolAddress(&pbnshift, g_bnshift);
    cudaGetSymbolAddress(&pw0p,  g_w0pack);
    cudaGetSymbolAddress(&pw1p,  g_w1pack);
    cudaGetSymbolAddress(&pdeg,   g_deg);
    cudaGetSymbolAddress(&pcnt,   g_cnt);
    cudaGetSymbolAddress(&pincl,  g_incl);
    cudaGetSymbolAddress(&prowptr,g_rowptr);
    cudaGetSymbolAddress(&padj,   g_adj);
    cudaGetSymbolAddress(&pbsum,  g_bsum);

    cudaFuncSetAttribute(gemm0_tf32_att_kernel,
                         cudaFuncAttributeMaxDynamicSharedMemorySize, GEMM_SMEM);
    cudaFuncSetAttribute(gemm1_tf32_att_kernel,
                         cudaFuncAttributeMaxDynamicSharedMemorySize, GEMM_SMEM);

    // launch order keeps gemm0 as the 4th launch (ncu capture window)
    wsplit_kernel<<<48, 256>>>(W0, W1, (uint4*)pw0p, (uint4*)pw1p);         // 1
    zero2_kernel<<<128, 256>>>((int*)pdeg, (int*)pcnt, Nn);                 // 2
    deg_kernel<<<(ET + 255) / 256, 256>>>(ei, (int*)pdeg);                  // 3
    gemm0_tf32_att_kernel<<<(Nn + 63) / 64, 256, GEMM_SMEM>>>(              // 4
        (const float4*)data, (const uint4*)pw0p, (float*)ph0, Nn,
        asrc0, adst0, (float*)pa0s, (float*)pa0d);
    scan1_kernel<<<NB1, SCAN_B>>>((int*)pdeg, (int*)pincl, (int*)pbsum);    // 5
    scan3_kernel<<<(Nn + 255) / 256, 256>>>((int*)pincl, (int*)pbsum,       // 6
                                            (int*)prowptr);
    fill_kernel<<<(ET + 255) / 256, 256>>>(ei, (int*)prowptr, (int*)pcnt,   // 7
                                           (int*)padj);
    agg0_kernel<<<(Nn + 7) / 8, 256>>>((int*)prowptr, (int*)padj,           // 8
                                       (float*)pa0s, (float*)pa0d,
                                       (const float4*)ph0, (float4*)px1, bias0);
    bnsum_kernel<<<BN_BLOCKS, C0>>>((float*)px1, (float*)pbps, (float*)pbpq); // 9
    bnred_kernel<<<1, C0>>>((float*)pbps, (float*)pbpq, gam0, bet0,         // 10
                            (float*)pbnscale, (float*)pbnshift);
    gemm1_tf32_att_kernel<<<(Nn + 63) / 64, 256, GEMM_SMEM>>>(              // 11
        (const float4*)px1, (const uint4*)pw1p, (float*)ph1, Nn,
        (const float4*)pbnscale, (const float4*)pbnshift,
        asrc1, adst1, (float*)pa1s, (float*)pa1d);
    agg1_kernel<<<(Nn + 7) / 8, 256>>>((int*)prowptr, (int*)padj,           // 12
                                       (float*)pa1s, (float*)pa1d,
                                       (const float2*)ph1, (float2*)out, bias1);
}

// round 10
// speedup vs baseline: 1.2941x; 1.0260x over previous
#include <cuda_runtime.h>
#include <cstdint>

// ---------------- problem constants ----------------
constexpr int Nn   = 50000;          // nodes
constexpr int Ee   = 800000;         // edges (w/o self loops)
constexpr int ET   = Ee + Nn;        // edges incl. self loops
constexpr int IND  = 128;            // input dim
constexpr int C0   = 128;            // layer0 out channels (2 heads * 64)
constexpr int OUTD = 64;             // layer1 out channels (1 head)
constexpr float NEG_SLOPE = 0.2f;
constexpr float BN_EPS    = 1e-5f;

constexpr int SCAN_B = 1024;
constexpr int NB1    = (Nn + SCAN_B - 1) / SCAN_B;   // 49
constexpr int BN_BLOCKS = 512;

constexpr int ROWW = 264;            // smem words per row (264 mod 32 == 8 -> conflict-free)
constexpr int GEMM_SMEM = 64 * ROWW * 4;   // 67584 bytes

// ---------------- device scratch ----------------
__device__ float4 g_h0[Nn * C0 / 4];     // x@W0
__device__ float4 g_x1[Nn * C0 / 4];     // layer0 out (pre-BN)
__device__ float4 g_h1[Nn * OUTD / 4];   // x1@W1
__device__ float  g_a0s[Nn * 2];
__device__ float  g_a0d[Nn * 2];
__device__ float  g_a1s[Nn];
__device__ float  g_a1d[Nn];
__device__ float  g_bps[BN_BLOCKS * C0];
__device__ float  g_bpq[BN_BLOCKS * C0];
__device__ float4 g_bnscale[C0 / 4];
__device__ float4 g_bnshift[C0 / 4];
__device__ uint4  g_w0pack[128 * 16 * 4];    // [c][kt][lr] {hi0,hi1,lo0,lo1}
__device__ uint4  g_w1pack[64 * 16 * 4];
// CSR
__device__ int    g_deg   [Nn];
__device__ int    g_cnt   [Nn];
__device__ int    g_incl  [Nn];
__device__ int    g_rowptr[Nn + 1];
__device__ int    g_adj   [ET];
__device__ int    g_bsum  [NB1];

__device__ __forceinline__ float lrelu(float e) {
    return e > 0.f ? e : NEG_SLOPE * e;
}

__device__ __forceinline__ uint32_t f2tf32(float f) {
    uint32_t u;
    asm("cvt.rna.tf32.f32 %0, %1;" : "=r"(u) : "f"(f));
    return u;
}

__device__ __forceinline__ void mma_tf32(float4& c, const uint32_t* a, const uint32_t* b) {
    asm volatile(
        "mma.sync.aligned.m16n8k8.row.col.f32.tf32.tf32.f32 "
        "{%0,%1,%2,%3}, {%4,%5,%6,%7}, {%8,%9}, {%0,%1,%2,%3};"
        : "+f"(c.x), "+f"(c.y), "+f"(c.z), "+f"(c.w)
        : "r"(a[0]), "r"(a[1]), "r"(a[2]), "r"(a[3]), "r"(b[0]), "r"(b[1]));
}

// ---------------- zero both CSR counter arrays in one launch ----------------
__global__ void zero2_kernel(int* p0, int* p1, int n) {
    int i = blockIdx.x * blockDim.x + threadIdx.x;
    for (; i < n; i += gridDim.x * blockDim.x) { p0[i] = 0; p1[i] = 0; }
}

// -------- pre-split W0/W1 into tf32 hi/lo fragment-ordered uint4 ------------
__global__ void wsplit_kernel(const float* __restrict__ W0,
                              const float* __restrict__ W1,
                              uint4* __restrict__ w0p, uint4* __restrict__ w1p) {
    int idx = blockIdx.x * blockDim.x + threadIdx.x;
    if (idx < 128 * 64) {                       // W0: c<128, 16 kt, 4 lr
        int c = idx >> 6, t = idx & 63;
        int kt = t >> 2, lr = t & 3, k0 = 8 * kt;
        float f0 = W0[(k0 + lr) * 128 + c];
        float f1 = W0[(k0 + lr + 4) * 128 + c];
        uint32_t h0 = f2tf32(f0), h1 = f2tf32(f1);
        uint32_t l0 = f2tf32(f0 - __uint_as_float(h0));
        uint32_t l1 = f2tf32(f1 - __uint_as_float(h1));
        w0p[idx] = make_uint4(h0, h1, l0, l1);
    } else if (idx < 128 * 64 + 64 * 64) {      // W1: c<64, 16 kt, 4 lr
        int j = idx - 128 * 64;
        int c = j >> 6, t = j & 63;
        int kt = t >> 2, lr = t & 3, k0 = 8 * kt;
        float f0 = W1[(k0 + lr) * 64 + c];
        float f1 = W1[(k0 + lr + 4) * 64 + c];
        uint32_t h0 = f2tf32(f0), h1 = f2tf32(f1);
        uint32_t l0 = f2tf32(f0 - __uint_as_float(h0));
        uint32_t l1 = f2tf32(f1 - __uint_as_float(h1));
        w1p[c * 64 + kt * 4 + lr] = make_uint4(h0, h1, l0, l1);
    }
}

// ---------------- CSR build ----------------
__global__ void deg_kernel(const int* __restrict__ ei, int* __restrict__ deg) {
    int i = blockIdx.x * blockDim.x + threadIdx.x;
    if (i >= ET) return;
    int dst = (i < Ee) ? ei[Ee + i] : (i - Ee);
    atomicAdd(&deg[dst], 1);
}

__global__ void scan1_kernel(const int* __restrict__ deg,
                             int* __restrict__ incl, int* __restrict__ bsum) {
    __shared__ int wsum[32];
    int tid  = threadIdx.x;
    int lane = tid & 31, wid = tid >> 5;
    int i = blockIdx.x * SCAN_B + tid;
    int v = (i < Nn) ? deg[i] : 0;
#pragma unroll
    for (int off = 1; off < 32; off <<= 1) {
        int t = __shfl_up_sync(0xffffffffu, v, off);
        if (lane >= off) v += t;
    }
    if (lane == 31) wsum[wid] = v;
    __syncthreads();
    if (wid == 0) {
        int w = wsum[lane];
#pragma unroll
        for (int off = 1; off < 32; off <<= 1) {
            int t = __shfl_up_sync(0xffffffffu, w, off);
            if (lane >= off) w += t;
        }
        wsum[lane] = w;
    }
    __syncthreads();
    if (wid > 0) v += wsum[wid - 1];
    if (i < Nn) incl[i] = v;
    if (tid == SCAN_B - 1) bsum[blockIdx.x] = v;
}

__global__ void scan3_kernel(const int* __restrict__ incl,
                             const int* __restrict__ bsum,
                             int* __restrict__ rowptr) {
    __shared__ int bs[NB1];
    for (int k = threadIdx.x; k < NB1; k += blockDim.x) bs[k] = bsum[k];
    __syncthreads();
    int i = blockIdx.x * blockDim.x + threadIdx.x;
    if (i == 0) rowptr[0] = 0;
    if (i >= Nn) return;
    int b = i / SCAN_B;
    int off = 0;
    for (int k = 0; k < b; k++) off += bs[k];
    rowptr[i + 1] = incl[i] + off;
}

__global__ void fill_kernel(const int* __restrict__ ei,
                            const int* __restrict__ rowptr,
                            int* __restrict__ cnt, int* __restrict__ adj) {
    int i = blockIdx.x * blockDim.x + threadIdx.x;
    if (i >= ET) return;
    int src, dst;
    if (i < Ee) { src = ei[i]; dst = ei[Ee + i]; }
    else        { src = dst = i - Ee; }
    int pos = rowptr[dst] + atomicAdd(&cnt[dst], 1);
    adj[pos] = src;
}

// ------ GEMM0 tf32x3: hi/lo-interleaved smem A, pre-split B, fused attdot ---
// 256 threads = 8 warps in 2(m) x 4(n): warp tile m32 x n32, block 64 x 128.
__global__ void gemm0_tf32_att_kernel(const float4* __restrict__ X4,
                                      const uint4* __restrict__ Wp,
                                      float* __restrict__ Y, int nrows,
                                      const float* __restrict__ att_src,
                                      const float* __restrict__ att_dst,
                                      float* __restrict__ a_s,
                                      float* __restrict__ a_d) {
    extern __shared__ uint32_t aw[];                 // [64][ROWW]: {hi,lo} per k
    __shared__ float reds[8][32], redd[8][32];
    const int tid  = threadIdx.x;
    const int lane = tid & 31;
    const int warp = tid >> 5;
    const int warp_m = warp >> 2;
    const int warp_n = warp & 3;
    const int row0 = blockIdx.x * 64;

    // stage X, tf32 hi/lo interleaved: word (r*ROWW + 2k) = hi, +1 = lo
    for (int i = tid; i < 64 * 32; i += 256) {
        int r = i >> 5, kk = i & 31;
        int row = row0 + r;
        float4 v = (row < nrows) ? X4[(size_t)row * 32 + kk]
                                 : make_float4(0.f, 0.f, 0.f, 0.f);
        float f[4] = {v.x, v.y, v.z, v.w};
        uint32_t h[4], l[4];
#pragma unroll
        for (int j = 0; j < 4; j++) {
            h[j] = f2tf32(f[j]);
            l[j] = f2tf32(f[j] - __uint_as_float(h[j]));
        }
        uint4* dst = reinterpret_cast<uint4*>(&aw[r * ROWW + kk * 8]);
        dst[0] = make_uint4(h[0], l[0], h[1], l[1]);
        dst[1] = make_uint4(h[2], l[2], h[3], l[3]);
    }
    __syncthreads();

    float4 acc[2][4];
#pragma unroll
    for (int mt = 0; mt < 2; mt++)
#pragma unroll
        for (int nt = 0; nt < 4; nt++) acc[mt][nt] = make_float4(0.f, 0.f, 0.f, 0.f);

    const int mrow = warp_m * 32;
    const int ncol = warp_n * 32;
    const int lq = lane >> 2;
    const int lr = lane & 3;

#pragma unroll 4
    for (int kt = 0; kt < 16; kt++) {
        const int k0 = kt * 8;
        uint32_t ahi[2][4], alo[2][4];
#pragma unroll
        for (int mt = 0; mt < 2; mt++) {
            int rb = mrow + mt * 16 + lq;
            uint2 q0 = *reinterpret_cast<const uint2*>(&aw[rb * ROWW + (k0 + lr) * 2]);
            uint2 q1 = *reinterpret_cast<const uint2*>(&aw[(rb + 8) * ROWW + (k0 + lr) * 2]);
            uint2 q2 = *reinterpret_cast<const uint2*>(&aw[rb * ROWW + (k0 + lr + 4) * 2]);
            uint2 q3 = *reinterpret_cast<const uint2*>(&aw[(rb + 8) * ROWW + (k0 + lr + 4) * 2]);
            ahi[mt][0] = q0.x; alo[mt][0] = q0.y;
            ahi[mt][1] = q1.x; alo[mt][1] = q1.y;
            ahi[mt][2] = q2.x; alo[mt][2] = q2.y;
            ahi[mt][3] = q3.x; alo[mt][3] = q3.y;
        }
#pragma unroll
        for (int nt = 0; nt < 4; nt++) {
            int col = ncol + nt * 8 + lq;
            uint4 B = Wp[col * 64 + kt * 4 + lr];
            uint32_t bhi[2] = {B.x, B.y};
            uint32_t blo[2] = {B.z, B.w};
#pragma unroll
            for (int mt = 0; mt < 2; mt++) {
                mma_tf32(acc[mt][nt], alo[mt], bhi);
                mma_tf32(acc[mt][nt], ahi[mt], blo);
                mma_tf32(acc[mt][nt], ahi[mt], bhi);
            }
        }
    }

    // epilogue: store Y + fused attention dots
    float ps[2][2] = {{0.f, 0.f}, {0.f, 0.f}};
    float pd[2][2] = {{0.f, 0.f}, {0.f, 0.f}};
#pragma unroll
    for (int mt = 0; mt < 2; mt++) {
#pragma unroll
        for (int nt = 0; nt < 4; nt++) {
            float4 a = acc[mt][nt];
            int col = ncol + nt * 8 + lr * 2;
            int row = row0 + mrow + mt * 16 + lq;
            float s0 = att_src[col], s1 = att_src[col + 1];
            float d0 = att_dst[col], d1 = att_dst[col + 1];
            ps[mt][0] += a.x * s0 + a.y * s1;
            pd[mt][0] += a.x * d0 + a.y * d1;
            ps[mt][1] += a.z * s0 + a.w * s1;
            pd[mt][1] += a.z * d0 + a.w * d1;
            if (row < nrows)
                *reinterpret_cast<float2*>(&Y[(size_t)row * 128 + col]) = make_float2(a.x, a.y);
            if (row + 8 < nrows)
                *reinterpret_cast<float2*>(&Y[(size_t)(row + 8) * 128 + col]) = make_float2(a.z, a.w);
        }
#pragma unroll
        for (int half = 0; half < 2; half++) {
#pragma unroll
            for (int off = 1; off <= 2; off <<= 1) {
                ps[mt][half] += __shfl_xor_sync(0xffffffffu, ps[mt][half], off);
                pd[mt][half] += __shfl_xor_sync(0xffffffffu, pd[mt][half], off);
            }
            if (lr == 0) {
                reds[warp][mt * 16 + half * 8 + lq] = ps[mt][half];
                redd[warp][mt * 16 + half * 8 + lq] = pd[mt][half];
            }
        }
    }
    __syncthreads();
    if (tid < 128) {
        int r = tid & 63, h = tid >> 6;
        int grow = row0 + r;
        if (grow < nrows) {
            int wm = r >> 5, rl = r & 31;
            int wA = wm * 4 + 2 * h;
            a_s[grow * 2 + h] = reds[wA][rl] + reds[wA + 1][rl];
            a_d[grow * 2 + h] = redd[wA][rl] + redd[wA + 1][rl];
        }
    }
}

// -- GEMM1 tf32x3 (BN+ELU fused on X) + fused attdot (H=1, 64 cols) ----------
// 256 threads = 8 warps in 4(m) x 2(n): warp tile m16 x n32, block 64 x 64.
__global__ void gemm1_tf32_att_kernel(const float4* __restrict__ X4,
                                      const uint4* __restrict__ Wp,
                                      float* __restrict__ Y, int nrows,
                                      const float4* __restrict__ sc4,
                                      const float4* __restrict__ sh4,
                                      const float* __restrict__ att_src,
                                      const float* __restrict__ att_dst,
                                      float* __restrict__ a_s,
                                      float* __restrict__ a_d) {
    extern __shared__ uint32_t aw[];                 // [64][ROWW]
    __shared__ float reds[8][16], redd[8][16];
    const int tid  = threadIdx.x;
    const int lane = tid & 31;
    const int warp = tid >> 5;
    const int warp_m = warp >> 1;                    // 0..3 -> rows 16*wm
    const int warp_n = warp & 1;                     // 0..1 -> cols 32*wn
    const int row0 = blockIdx.x * 64;

    // stage X with BN+ELU, tf32 hi/lo interleaved
    for (int i = tid; i < 64 * 32; i += 256) {
        int r = i >> 5, kk = i & 31;
        int row = row0 + r;
        float4 raw = (row < nrows) ? X4[(size_t)row * 32 + kk]
                                   : make_float4(0.f, 0.f, 0.f, 0.f);
        float4 sc = sc4[kk], sh = sh4[kk];
        float f[4];
        f[0] = raw.x * sc.x + sh.x;
        f[1] = raw.y * sc.y + sh.y;
        f[2] = raw.z * sc.z + sh.z;
        f[3] = raw.w * sc.w + sh.w;
        uint32_t h[4], l[4];
#pragma unroll
        for (int j = 0; j < 4; j++) {
            f[j] = f[j] > 0.f ? f[j] : expm1f(f[j]);
            h[j] = f2tf32(f[j]);
            l[j] = f2tf32(f[j] - __uint_as_float(h[j]));
        }
        uint4* dst = reinterpret_cast<uint4*>(&aw[r * ROWW + kk * 8]);
        dst[0] = make_uint4(h[0], l[0], h[1], l[1]);
        dst[1] = make_uint4(h[2], l[2], h[3], l[3]);
    }
    __syncthreads();

    float4 acc[4];
#pragma unroll
    for (int nt = 0; nt < 4; nt++) acc[nt] = make_float4(0.f, 0.f, 0.f, 0.f);

    const int mrow = warp_m * 16;
    const int ncol = warp_n * 32;
    const int lq = lane >> 2;
    const int lr = lane & 3;

#pragma unroll 4
    for (int kt = 0; kt < 16; kt++) {
        const int k0 = kt * 8;
        uint2 q0 = *reinterpret_cast<const uint2*>(&aw[(mrow + lq) * ROWW + (k0 + lr) * 2]);
        uint2 q1 = *reinterpret_cast<const uint2*>(&aw[(mrow + 8 + lq) * ROWW + (k0 + lr) * 2]);
        uint2 q2 = *reinterpret_cast<const uint2*>(&aw[(mrow + lq) * ROWW + (k0 + lr + 4) * 2]);
        uint2 q3 = *reinterpret_cast<const uint2*>(&aw[(mrow + 8 + lq) * ROWW + (k0 + lr + 4) * 2]);
        uint32_t ahi[4] = {q0.x, q1.x, q2.x, q3.x};
        uint32_t alo[4] = {q0.y, q1.y, q2.y, q3.y};
#pragma unroll
        for (int nt = 0; nt < 4; nt++) {
            int col = ncol + nt * 8 + lq;
            uint4 B = Wp[col * 64 + kt * 4 + lr];
            uint32_t bhi[2] = {B.x, B.y};
            uint32_t blo[2] = {B.z, B.w};
            mma_tf32(acc[nt], alo, bhi);
            mma_tf32(acc[nt], ahi, blo);
            mma_tf32(acc[nt], ahi, bhi);
        }
    }

    // epilogue
    float ps[2] = {0.f, 0.f}, pd[2] = {0.f, 0.f};
#pragma unroll
    for (int nt = 0; nt < 4; nt++) {
        float4 a = acc[nt];
        int col = ncol + nt * 8 + lr * 2;
        int row = row0 + mrow + lq;
        float s0 = att_src[col], s1 = att_src[col + 1];
        float d0 = att_dst[col], d1 = att_dst[col + 1];
        ps[0] += a.x * s0 + a.y * s1;
        pd[0] += a.x * d0 + a.y * d1;
        ps[1] += a.z * s0 + a.w * s1;
        pd[1] += a.z * d0 + a.w * d1;
        if (row < nrows)
            *reinterpret_cast<float2*>(&Y[(size_t)row * 64 + col]) = make_float2(a.x, a.y);
        if (row + 8 < nrows)
            *reinterpret_cast<float2*>(&Y[(size_t)(row + 8) * 64 + col]) = make_float2(a.z, a.w);
    }
#pragma unroll
    for (int half = 0; half < 2; half++) {
#pragma unroll
        for (int off = 1; off <= 2; off <<= 1) {
            ps[half] += __shfl_xor_sync(0xffffffffu, ps[half], off);
            pd[half] += __shfl_xor_sync(0xffffffffu, pd[half], off);
        }
        if (lr == 0) {
            reds[warp][half * 8 + lq] = ps[half];
            redd[warp][half * 8 + lq] = pd[half];
        }
    }
    __syncthreads();
    if (tid < 64) {
        int grow = row0 + tid;
        if (grow < nrows) {
            int wm = tid >> 4, rl = tid & 15;
            a_s[grow] = reds[wm * 2][rl] + reds[wm * 2 + 1][rl];
            a_d[grow] = redd[wm * 2][rl] + redd[wm * 2 + 1][rl];
        }
    }
}

// ------- layer0: fused segment softmax + gather-aggregate + bias (warp/node) -
__global__ void agg0_kernel(const int* __restrict__ rowptr,
                            const int* __restrict__ adj,
                            const float* __restrict__ a_s,
                            const float* __restrict__ a_d,
                            const float4* __restrict__ h,
                            float4* __restrict__ out,
                            const float* __restrict__ bias) {
    int node = (blockIdx.x * blockDim.x + threadIdx.x) >> 5;
    int lane = threadIdx.x & 31;
    if (node >= Nn) return;
    const int beg = rowptr[node], end = rowptr[node + 1];
    const float ad0 = a_d[node * 2 + 0];
    const float ad1 = a_d[node * 2 + 1];

    float m0 = -1e30f, m1 = -1e30f;
    for (int j = beg + lane; j < end; j += 32) {
        int s = adj[j];
        m0 = fmaxf(m0, lrelu(a_s[s * 2 + 0] + ad0));
        m1 = fmaxf(m1, lrelu(a_s[s * 2 + 1] + ad1));
    }
#pragma unroll
    for (int off = 16; off > 0; off >>= 1) {
        m0 = fmaxf(m0, __shfl_xor_sync(0xffffffffu, m0, off));
        m1 = fmaxf(m1, __shfl_xor_sync(0xffffffffu, m1, off));
    }

    const bool hi = (lane >= 16);
    float den0 = 0.f, den1 = 0.f;
    float4 acc = make_float4(0.f, 0.f, 0.f, 0.f);
    int j = beg;
    for (; j + 1 < end; j += 2) {
        int s0 = adj[j], s1 = adj[j + 1];
        float4 v0 = h[(size_t)s0 * (C0 / 4) + lane];
        float4 v1 = h[(size_t)s1 * (C0 / 4) + lane];
        float e00 = __expf(lrelu(a_s[s0 * 2 + 0] + ad0) - m0);
        float e01 = __expf(lrelu(a_s[s0 * 2 + 1] + ad1) - m1);
        float e10 = __expf(lrelu(a_s[s1 * 2 + 0] + ad0) - m0);
        float e11 = __expf(lrelu(a_s[s1 * 2 + 1] + ad1) - m1);
        den0 += e00 + e10; den1 += e01 + e11;
        float sc0 = hi ? e01 : e00;
        float sc1 = hi ? e11 : e10;
        acc.x += v0.x * sc0 + v1.x * sc1;
        acc.y += v0.y * sc0 + v1.y * sc1;
        acc.z += v0.z * sc0 + v1.z * sc1;
        acc.w += v0.w * sc0 + v1.w * sc1;
    }
    if (j < end) {
        int s = adj[j];
        float4 v = h[(size_t)s * (C0 / 4) + lane];
        float ex0 = __expf(lrelu(a_s[s * 2 + 0] + ad0) - m0);
        float ex1 = __expf(lrelu(a_s[s * 2 + 1] + ad1) - m1);
        den0 += ex0; den1 += ex1;
        float sc = hi ? ex1 : ex0;
        acc.x += v.x * sc; acc.y += v.y * sc;
        acc.z += v.z * sc; acc.w += v.w * sc;
    }
    float inv = 1.f / ((hi ? den1 : den0) + 1e-16f);
    int c = lane * 4;
    float4 b4 = *reinterpret_cast<const float4*>(bias + c);
    float4 o;
    o.x = acc.x * inv + b4.x;
    o.y = acc.y * inv + b4.y;
    o.z = acc.z * inv + b4.z;
    o.w = acc.w * inv + b4.w;
    out[(size_t)node * (C0 / 4) + lane] = o;
}

// ------- layer1: fused segment softmax + gather-aggregate + bias -------------
__global__ void agg1_kernel(const int* __restrict__ rowptr,
                            const int* __restrict__ adj,
                            const float* __restrict__ a_s,
                            const float* __restrict__ a_d,
                            const float2* __restrict__ h,
                            float2* __restrict__ out,
                            const float* __restrict__ bias) {
    int node = (blockIdx.x * blockDim.x + threadIdx.x) >> 5;
    int lane = threadIdx.x & 31;
    if (node >= Nn) return;
    const int beg = rowptr[node], end = rowptr[node + 1];
    const float ad = a_d[node];

    float m = -1e30f;
    for (int j = beg + lane; j < end; j += 32) {
        int s = adj[j];
        m = fmaxf(m, lrelu(a_s[s] + ad));
    }
#pragma unroll
    for (int off = 16; off > 0; off >>= 1)
        m = fmaxf(m, __shfl_xor_sync(0xffffffffu, m, off));

    float den = 0.f;
    float2 acc = make_float2(0.f, 0.f);
    int j = beg;
    for (; j + 1 < end; j += 2) {
        int s0 = adj[j], s1 = adj[j + 1];
        float2 v0 = h[(size_t)s0 * (OUTD / 2) + lane];
        float2 v1 = h[(size_t)s1 * (OUTD / 2) + lane];
        float e0 = __expf(lrelu(a_s[s0] + ad) - m);
        float e1 = __expf(lrelu(a_s[s1] + ad) - m);
        den += e0 + e1;
        acc.x += v0.x * e0 + v1.x * e1;
        acc.y += v0.y * e0 + v1.y * e1;
    }
    if (j < end) {
        int s = adj[j];
        float2 v = h[(size_t)s * (OUTD / 2) + lane];
        float ex = __expf(lrelu(a_s[s] + ad) - m);
        den += ex;
        acc.x += v.x * ex; acc.y += v.y * ex;
    }
    float inv = 1.f / (den + 1e-16f);
    int c = lane * 2;
    float2 o;
    o.x = acc.x * inv + bias[c + 0];
    o.y = acc.y * inv + bias[c + 1];
    out[(size_t)node * (OUTD / 2) + lane] = o;
}

// ---------------- BN partial statistics (deterministic) ----------------
__global__ void bnsum_kernel(const float* __restrict__ x,
                             float* __restrict__ bps, float* __restrict__ bpq) {
    int c = threadIdx.x;                         // blockDim.x == 128
    float lsum = 0.f, lsq = 0.f;
    for (int row = blockIdx.x; row < Nn; row += gridDim.x) {
        float v = x[(size_t)row * C0 + c];
        lsum += v;
        lsq  += v * v;
    }
    bps[blockIdx.x * C0 + c] = lsum;
    bpq[blockIdx.x * C0 + c] = lsq;
}

__global__ void bnred_kernel(const float* __restrict__ bps,
                             const float* __restrict__ bpq,
                             const float* __restrict__ gamma,
                             const float* __restrict__ beta,
                             float* __restrict__ bnscale,
                             float* __restrict__ bnshift) {
    int c = threadIdx.x;                         // one block of 128 threads
    float s = 0.f, q = 0.f;
    for (int b = 0; b < BN_BLOCKS; b++) {
        s += bps[b * C0 + c];
        q += bpq[b * C0 + c];
    }
    const float invN = 1.0f / (float)Nn;
    float mu  = s * invN;
    float var = q * invN - mu * mu;
    float sc  = gamma[c] * rsqrtf(var + BN_EPS);
    bnscale[c] = sc;
    bnshift[c] = beta[c] - mu * sc;
}

// ---------------- launch ----------------
extern "C" void kernel_launch(void* const* d_in, const int* in_sizes, int n_in,
                              void* d_out, int out_size) {
    const float* data  = (const float*)d_in[0];
    const int*   ei    = (const int*)d_in[1];     // int32 (JAX x64 disabled)
    const float* W0    = (const float*)d_in[2];
    const float* asrc0 = (const float*)d_in[3];
    const float* adst0 = (const float*)d_in[4];
    const float* bias0 = (const float*)d_in[5];
    const float* gam0  = (const float*)d_in[6];
    const float* bet0  = (const float*)d_in[7];
    const float* W1    = (const float*)d_in[8];
    const float* asrc1 = (const float*)d_in[9];
    const float* adst1 = (const float*)d_in[10];
    const float* bias1 = (const float*)d_in[11];
    float* out = (float*)d_out;

    void *ph0, *px1, *ph1, *pa0s, *pa0d, *pa1s, *pa1d;
    void *pbps, *pbpq, *pbnscale, *pbnshift, *pw0p, *pw1p;
    void *pdeg, *pcnt, *pincl, *prowptr, *padj, *pbsum;
    cudaGetSymbolAddress(&ph0,  g_h0);
    cudaGetSymbolAddress(&px1,  g_x1);
    cudaGetSymbolAddress(&ph1,  g_h1);
    cudaGetSymbolAddress(&pa0s, g_a0s);
    cudaGetSymbolAddress(&pa0d, g_a0d);
    cudaGetSymbolAddress(&pa1s, g_a1s);
    cudaGetSymbolAddress(&pa1d, g_a1d);
    cudaGetSymbolAddress(&pbps,     g_bps);
    cudaGetSymbolAddress(&pbpq,     g_bpq);
    cudaGetSymbolAddress(&pbnscale, g_bnscale);
    cudaGetSymbolAddress(&pbnshift, g_bnshift);
    cudaGetSymbolAddress(&pw0p,  g_w0pack);
    cudaGetSymbolAddress(&pw1p,  g_w1pack);
    cudaGetSymbolAddress(&pdeg,   g_deg);
    cudaGetSymbolAddress(&pcnt,   g_cnt);
    cudaGetSymbolAddress(&pincl,  g_incl);
    cudaGetSymbolAddress(&prowptr,g_rowptr);
    cudaGetSymbolAddress(&padj,   g_adj);
    cudaGetSymbolAddress(&pbsum,  g_bsum);

    cudaFuncSetAttribute(gemm0_tf32_att_kernel,
                         cudaFuncAttributeMaxDynamicSharedMemorySize, GEMM_SMEM);
    cudaFuncSetAttribute(gemm1_tf32_att_kernel,
                         cudaFuncAttributeMaxDynamicSharedMemorySize, GEMM_SMEM);

    // launch order keeps gemm0 as the 4th launch (ncu capture window)
    wsplit_kernel<<<48, 256>>>(W0, W1, (uint4*)pw0p, (uint4*)pw1p);         // 1
    zero2_kernel<<<128, 256>>>((int*)pdeg, (int*)pcnt, Nn);                 // 2
    deg_kernel<<<(ET + 255) / 256, 256>>>(ei, (int*)pdeg);                  // 3
    gemm0_tf32_att_kernel<<<(Nn + 63) / 64, 256, GEMM_SMEM>>>(              // 4
        (const float4*)data, (const uint4*)pw0p, (float*)ph0, Nn,
        asrc0, adst0, (float*)pa0s, (float*)pa0d);
    scan1_kernel<<<NB1, SCAN_B>>>((int*)pdeg, (int*)pincl, (int*)pbsum);    // 5
    scan3_kernel<<<(Nn + 255) / 256, 256>>>((int*)pincl, (int*)pbsum,       // 6
                                            (int*)prowptr);
    fill_kernel<<<(ET + 255) / 256, 256>>>(ei, (int*)prowptr, (int*)pcnt,   // 7
                                           (int*)padj);
    agg0_kernel<<<(Nn + 7) / 8, 256>>>((int*)prowptr, (int*)padj,           // 8
                                       (float*)pa0s, (float*)pa0d,
                                       (const float4*)ph0, (float4*)px1, bias0);
    bnsum_kernel<<<BN_BLOCKS, C0>>>((float*)px1, (float*)pbps, (float*)pbpq); // 9
    bnred_kernel<<<1, C0>>>((float*)pbps, (float*)pbpq, gam0, bet0,         // 10
                            (float*)pbnscale, (float*)pbnshift);
    gemm1_tf32_att_kernel<<<(Nn + 63) / 64, 256, GEMM_SMEM>>>(              // 11
        (const float4*)px1, (const uint4*)pw1p, (float*)ph1, Nn,
        (const float4*)pbnscale, (const float4*)pbnshift,
        asrc1, adst1, (float*)pa1s, (float*)pa1d);
    agg1_kernel<<<(Nn + 7) / 8, 256>>>((int*)prowptr, (int*)padj,           // 12
                                       (float*)pa1s, (float*)pa1d,
                                       (const float2*)ph1, (float2*)out, bias1);
}